// round 9
// baseline (speedup 1.0000x reference)
#include <cuda_runtime.h>
#include <cuda_bf16.h>
#include <cstdint>

// ---------------- problem constants ----------------
#define N_NODES 100000
#define IN_CH   512
#define HID_CH  256
#define OUT_CH  32
#define N_EDGES 1600000
#define K_STEPS 10
#define ALPHA   0.1f

// ---------------- device scratch (no allocations allowed) ----------------
__device__ float g_h0[(size_t)N_NODES * OUT_CH];
__device__ float g_ha[(size_t)N_NODES * OUT_CH];
__device__ float g_hb[(size_t)N_NODES * OUT_CH];
__device__ int   g_deg[N_NODES];
__device__ float g_selfc[N_NODES];
__device__ int   g_idx64;

// CSR (dst-sorted) for pull aggregation
__device__ int   g_rowptr[N_NODES + 1];
__device__ int   g_fill[N_NODES];
__device__ int   g_partial[256];
__device__ int2  g_csr[N_EDGES];       // {src, coef_bits}

// degree-bucketed node permutation (warp load balance)
#define MAXDEG 512
__device__ int   g_hist[MAXDEG];
__device__ int   g_hfill[MAXDEG];
__device__ int   g_perm[N_NODES];

// split-bf16 W1^T for the tensor-core GEMM ([n][k])
__device__ __align__(16) __nv_bfloat16 g_w1t_h[(size_t)HID_CH * IN_CH];
__device__ __align__(16) __nv_bfloat16 g_w1t_l[(size_t)HID_CH * IN_CH];

// ---------------- dtype detection ----------------
__global__ void detect_dtype_kernel(const int* __restrict__ ei32) {
    int t = threadIdx.x;
    int any = 0;
    for (int i = t; i < 1024; i += 32) any |= ei32[2 * i + 1];
#pragma unroll
    for (int o = 16; o; o >>= 1) any |= __shfl_xor_sync(0xffffffffu, any, o);
    if (t == 0) g_idx64 = (any == 0) ? 1 : 0;
}

__device__ __forceinline__ int load_idx(const void* ei, size_t pos, int is64) {
    long long v = is64 ? ((const long long*)ei)[pos] : (long long)((const int*)ei)[pos];
    if (v < 0) v = 0;
    if (v >= N_NODES) v = N_NODES - 1;
    return (int)v;
}

// ---------------- degree + histogram init ----------------
__global__ void init_deg_kernel() {
    int i = blockIdx.x * blockDim.x + threadIdx.x;
    if (i < N_NODES) g_deg[i] = 1;  // self-loop
    if (i < MAXDEG) { g_hist[i] = 0; g_hfill[i] = 0; }
}

__global__ void deg_edges_kernel(const void* __restrict__ ei) {
    int e = blockIdx.x * blockDim.x + threadIdx.x;
    if (e >= N_EDGES) return;
    int is64 = g_idx64;
    atomicAdd(&g_deg[load_idx(ei, (size_t)N_EDGES + e, is64)], 1);
}

// ---------------- CSR build: scan + fused fill; degree histogram ----------------
#define SCAN_BLK 512
__global__ void scanA_kernel() {   // exclusive scan of (deg-1), selfc, deg histogram
    __shared__ int s[SCAN_BLK];
    int t = threadIdx.x;
    int i = blockIdx.x * SCAN_BLK + t;
    int v = (i < N_NODES) ? (g_deg[i] - 1) : 0;
    if (i < N_NODES) {
        g_selfc[i] = 1.0f / (float)(v + 1);
        int d = v + 1; if (d >= MAXDEG) d = MAXDEG - 1;
        atomicAdd(&g_hist[d], 1);
    }
    s[t] = v;
    __syncthreads();
#pragma unroll
    for (int off = 1; off < SCAN_BLK; off <<= 1) {
        int x = (t >= off) ? s[t - off] : 0;
        __syncthreads();
        s[t] += x;
        __syncthreads();
    }
    if (i < N_NODES) g_rowptr[i] = s[t] - v;
    if (t == SCAN_BLK - 1) g_partial[blockIdx.x] = s[t];
}

__global__ void scanB_kernel(int nblocks) {    // single block scans partials
    __shared__ int s[256];
    int t = threadIdx.x;
    int v = (t < nblocks) ? g_partial[t] : 0;
    s[t] = v;
    __syncthreads();
#pragma unroll
    for (int off = 1; off < 256; off <<= 1) {
        int x = (t >= off) ? s[t - off] : 0;
        __syncthreads();
        s[t] += x;
        __syncthreads();
    }
    if (t < nblocks) g_partial[t] = s[t] - v;  // exclusive
}

__global__ void scanC_kernel() {               // add block offsets, zero fill
    int i = blockIdx.x * blockDim.x + threadIdx.x;
    if (i < N_NODES) {
        g_rowptr[i] += g_partial[i / SCAN_BLK];
        g_fill[i] = 0;
    }
    if (i == 0) g_rowptr[N_NODES] = N_EDGES;
}

__global__ void scan_hist_kernel() {           // exclusive scan of degree histogram
    __shared__ int s[MAXDEG];
    int t = threadIdx.x;
    int v = g_hist[t];
    s[t] = v;
    __syncthreads();
#pragma unroll
    for (int off = 1; off < MAXDEG; off <<= 1) {
        int x = (t >= off) ? s[t - off] : 0;
        __syncthreads();
        s[t] += x;
        __syncthreads();
    }
    g_hist[t] = s[t] - v;  // exclusive
}

__global__ void perm_kernel() {                // scatter nodes into degree buckets
    int i = blockIdx.x * blockDim.x + threadIdx.x;
    if (i >= N_NODES) return;
    int d = g_deg[i]; if (d >= MAXDEG) d = MAXDEG - 1;
    int pos = g_hist[d] + atomicAdd(&g_hfill[d], 1);
    g_perm[pos] = i;
}

// fused: read edge_index, compute coef, write CSR slot
__global__ void csr_fill_kernel(const void* __restrict__ ei) {
    int e = blockIdx.x * blockDim.x + threadIdx.x;
    if (e >= N_EDGES) return;
    int is64 = g_idx64;
    int s = load_idx(ei, e, is64);
    int d = load_idx(ei, (size_t)N_EDGES + e, is64);
    float c = rsqrtf((float)g_deg[s]) * rsqrtf((float)g_deg[d]);
    int pos = g_rowptr[d] + atomicAdd(&g_fill[d], 1);
    g_csr[pos] = make_int2(s, __float_as_int(c));
}

__global__ void init_h0_bias_kernel(const float* __restrict__ b2) {
    int i = blockIdx.x * blockDim.x + threadIdx.x;
    if (i < N_NODES * OUT_CH / 4) {
        const float4* b2v = (const float4*)b2;
        ((float4*)g_h0)[i] = b2v[i & 7];
    }
}

// ---------------- split-precision conversion ----------------
__device__ __forceinline__ void split1(float v, unsigned short& h, unsigned short& l) {
    __nv_bfloat16 hb = __float2bfloat16(v);
    float r = v - __bfloat162float(hb);
    __nv_bfloat16 lb = __float2bfloat16(r);
    h = *(unsigned short*)&hb;
    l = *(unsigned short*)&lb;
}

__global__ void split_w1t_kernel(const float* __restrict__ W1) {
    int i = blockIdx.x * blockDim.x + threadIdx.x;
    if (i >= HID_CH * IN_CH) return;
    int n = i >> 9;
    int k = i & 511;
    unsigned short h, l;
    split1(W1[(size_t)k * HID_CH + n], h, l);
    ((unsigned short*)g_w1t_h)[i] = h;
    ((unsigned short*)g_w1t_l)[i] = l;
}

// ---------------- tensor-core fused MLP ----------------
#define MMA_BF16(d, a, b0v, b1v)                                             \
    asm volatile(                                                            \
        "mma.sync.aligned.m16n8k16.row.col.f32.bf16.bf16.f32 "               \
        "{%0,%1,%2,%3}, {%4,%5,%6,%7}, {%8,%9}, {%0,%1,%2,%3};"              \
        : "+f"(d[0]), "+f"(d[1]), "+f"(d[2]), "+f"(d[3])                     \
        : "r"(a[0]), "r"(a[1]), "r"(a[2]), "r"(a[3]), "r"(b0v), "r"(b1v))

#define APITCH 40
#define CPITCH 68

__global__ __launch_bounds__(256)
void mlp_mma_kernel(const float* __restrict__ x,
                    const float* __restrict__ b1, const float* __restrict__ W2) {
    __shared__ __align__(16) union {
        struct {
            __nv_bfloat16 Ah[128 * APITCH], Al[128 * APITCH];
            __nv_bfloat16 Bh[128 * APITCH], Bl[128 * APITCH];
        } s1;
        struct { float Cs[128 * CPITCH]; float W2s[64 * 32]; } s2;
    } u;

    const int tid  = threadIdx.x;
    const int warp = tid >> 5;
    const int lane = tid & 31;
    const int wm = warp >> 1;
    const int wn = warp & 1;
    const int g  = lane >> 2;
    const int t  = lane & 3;
    const int brow = blockIdx.x * 128;
    const int bcol = blockIdx.y * 128;

    float acc[2][8][4];
#pragma unroll
    for (int i = 0; i < 2; i++)
#pragma unroll
        for (int j = 0; j < 8; j++)
#pragma unroll
            for (int r = 0; r < 4; r++) acc[i][j][r] = 0.0f;

    float4 pa[4];
    uint4  pbh[2], pbl[2];

    auto load_tile = [&](int k0) {
#pragma unroll
        for (int l = 0; l < 4; l++) {
            int idx = tid + l * 256;
            int row = idx >> 3;
            int seg = idx & 7;
            if (brow + row < N_NODES)
                pa[l] = *(const float4*)&x[(size_t)(brow + row) * IN_CH + k0 + seg * 4];
            else
                pa[l] = make_float4(0.f, 0.f, 0.f, 0.f);
        }
#pragma unroll
        for (int l = 0; l < 2; l++) {
            int idx = tid + l * 256;
            int row = idx >> 2;
            int seg = idx & 3;
            size_t go = (size_t)(bcol + row) * IN_CH + k0 + seg * 8;
            pbh[l] = *(const uint4*)&g_w1t_h[go];
            pbl[l] = *(const uint4*)&g_w1t_l[go];
        }
    };

    auto store_tile = [&]() {
#pragma unroll
        for (int l = 0; l < 4; l++) {
            int idx = tid + l * 256;
            int row = idx >> 3;
            int seg = idx & 7;
            ushort4 hh, ll;
            split1(pa[l].x, hh.x, ll.x);
            split1(pa[l].y, hh.y, ll.y);
            split1(pa[l].z, hh.z, ll.z);
            split1(pa[l].w, hh.w, ll.w);
            *(ushort4*)&u.s1.Ah[row * APITCH + seg * 4] = hh;
            *(ushort4*)&u.s1.Al[row * APITCH + seg * 4] = ll;
        }
#pragma unroll
        for (int l = 0; l < 2; l++) {
            int idx = tid + l * 256;
            int row = idx >> 2;
            int seg = idx & 3;
            *(uint4*)&u.s1.Bh[row * APITCH + seg * 8] = pbh[l];
            *(uint4*)&u.s1.Bl[row * APITCH + seg * 8] = pbl[l];
        }
    };

    load_tile(0);
    store_tile();
    __syncthreads();

    for (int k0 = 0; k0 < IN_CH; k0 += 32) {
        const bool more = (k0 + 32) < IN_CH;
        if (more) load_tile(k0 + 32);

#pragma unroll
        for (int kk = 0; kk < 32; kk += 16) {
            uint32_t ah[2][4], al[2][4];
#pragma unroll
            for (int i = 0; i < 2; i++) {
                int r = wm * 32 + i * 16 + g;
                int base = r * APITCH + kk + t * 2;
                ah[i][0] = *(const uint32_t*)&u.s1.Ah[base];
                ah[i][1] = *(const uint32_t*)&u.s1.Ah[base + 8 * APITCH];
                ah[i][2] = *(const uint32_t*)&u.s1.Ah[base + 8];
                ah[i][3] = *(const uint32_t*)&u.s1.Ah[base + 8 * APITCH + 8];
                al[i][0] = *(const uint32_t*)&u.s1.Al[base];
                al[i][1] = *(const uint32_t*)&u.s1.Al[base + 8 * APITCH];
                al[i][2] = *(const uint32_t*)&u.s1.Al[base + 8];
                al[i][3] = *(const uint32_t*)&u.s1.Al[base + 8 * APITCH + 8];
            }
#pragma unroll
            for (int j = 0; j < 8; j++) {
                int n = wn * 64 + j * 8 + g;
                int bb = n * APITCH + kk + t * 2;
                uint32_t bh0 = *(const uint32_t*)&u.s1.Bh[bb];
                uint32_t bh1 = *(const uint32_t*)&u.s1.Bh[bb + 8];
                uint32_t bl0 = *(const uint32_t*)&u.s1.Bl[bb];
                uint32_t bl1 = *(const uint32_t*)&u.s1.Bl[bb + 8];
#pragma unroll
                for (int i = 0; i < 2; i++) {
                    MMA_BF16(acc[i][j], ah[i], bh0, bh1);
                    MMA_BF16(acc[i][j], ah[i], bl0, bl1);
                    MMA_BF16(acc[i][j], al[i], bh0, bh1);
                }
            }
        }
        __syncthreads();
        if (more) {
            store_tile();
            __syncthreads();
        }
    }

    // ---- stage 2: relu(acc + b1) @ W2-slice, two 64-col halves ----
    const int c    = tid & 31;
    const int rgrp = tid >> 5;
    float sum[16];
#pragma unroll
    for (int rr = 0; rr < 16; rr++) sum[rr] = 0.0f;

#pragma unroll
    for (int h = 0; h < 2; h++) {
        __syncthreads();
        if (wn == h) {
#pragma unroll
            for (int i = 0; i < 2; i++)
#pragma unroll
                for (int j = 0; j < 8; j++) {
                    int row = wm * 32 + i * 16 + g;
                    int col = j * 8 + t * 2;
                    float bias0 = b1[bcol + h * 64 + col];
                    float bias1 = b1[bcol + h * 64 + col + 1];
                    float2 v0, v1;
                    v0.x = fmaxf(acc[i][j][0] + bias0, 0.0f);
                    v0.y = fmaxf(acc[i][j][1] + bias1, 0.0f);
                    v1.x = fmaxf(acc[i][j][2] + bias0, 0.0f);
                    v1.y = fmaxf(acc[i][j][3] + bias1, 0.0f);
                    *(float2*)&u.s2.Cs[row * CPITCH + col]       = v0;
                    *(float2*)&u.s2.Cs[(row + 8) * CPITCH + col] = v1;
                }
        }
#pragma unroll
        for (int l = 0; l < 8; l++) {
            int q = tid + l * 256;
            u.s2.W2s[q] = W2[(size_t)(bcol + h * 64 + (q >> 5)) * OUT_CH + (q & 31)];
        }
        __syncthreads();

#pragma unroll
        for (int k4 = 0; k4 < 16; k4++) {
            float w0 = u.s2.W2s[(k4 * 4 + 0) * 32 + c];
            float w1 = u.s2.W2s[(k4 * 4 + 1) * 32 + c];
            float w2 = u.s2.W2s[(k4 * 4 + 2) * 32 + c];
            float w3 = u.s2.W2s[(k4 * 4 + 3) * 32 + c];
#pragma unroll
            for (int rr = 0; rr < 16; rr++) {
                float4 cv = *(const float4*)&u.s2.Cs[(rgrp * 16 + rr) * CPITCH + k4 * 4];
                sum[rr] += cv.x * w0 + cv.y * w1 + cv.z * w2 + cv.w * w3;
            }
        }
    }

#pragma unroll
    for (int rr = 0; rr < 16; rr++) {
        int grow = brow + rgrp * 16 + rr;
        if (grow < N_NODES)
            atomicAdd(&g_h0[(size_t)grow * OUT_CH + c], sum[rr]);
    }
}

// ---------------- APPNP propagation: fused pull + combine ----------------
template <int SEL>
__device__ __forceinline__ const float* buf_const() {
    return SEL == 0 ? g_h0 : (SEL == 1 ? g_ha : g_hb);
}

// 8 lanes per node; lane q handles channels [4q, 4q+4). Nodes processed in
// degree-sorted order via g_perm so warps have uniform loop lengths.
template <int CUR, int NXT>
__global__ void pull_kernel(float* __restrict__ out) {
    const float* __restrict__ h = buf_const<CUR>();
    float* __restrict__ h_next =
        (NXT == 3) ? out : (NXT == 1 ? g_ha : g_hb);
    int t = blockIdx.x * blockDim.x + threadIdx.x;
    int slot = t >> 3;
    int q = t & 7;
    if (slot >= N_NODES) return;
    int node = g_perm[slot];

    int beg = g_rowptr[node];
    int end = g_rowptr[node + 1];

    float4 acc = make_float4(0.f, 0.f, 0.f, 0.f);
#pragma unroll 4
    for (int i = beg; i < end; i++) {
        int2 ed = __ldg(&g_csr[i]);
        float cf = __int_as_float(ed.y);
        float4 hv = *(const float4*)&h[(size_t)ed.x * OUT_CH + q * 4];
        acc.x += cf * hv.x;
        acc.y += cf * hv.y;
        acc.z += cf * hv.z;
        acc.w += cf * hv.w;
    }

    size_t i4 = (size_t)node * 8 + q;
    float sc = g_selfc[node];
    float4 hc = ((const float4*)h)[i4];
    float4 h0v = ((const float4*)g_h0)[i4];
    float4 r;
    r.x = ALPHA * h0v.x + (1.0f - ALPHA) * (acc.x + sc * hc.x);
    r.y = ALPHA * h0v.y + (1.0f - ALPHA) * (acc.y + sc * hc.y);
    r.z = ALPHA * h0v.z + (1.0f - ALPHA) * (acc.z + sc * hc.z);
    r.w = ALPHA * h0v.w + (1.0f - ALPHA) * (acc.w + sc * hc.w);
    ((float4*)h_next)[i4] = r;
}

// ---------------- host launch ----------------
extern "C" void kernel_launch(void* const* d_in, const int* in_sizes, int n_in,
                              void* d_out, int out_size) {
    const float* x = nullptr;  const void* ei = nullptr;
    const float* W1 = nullptr; const float* b1 = nullptr;
    const float* W2 = nullptr; const float* b2 = nullptr;
    for (int i = 0; i < n_in; i++) {
        switch (in_sizes[i]) {
            case N_NODES * IN_CH:   x  = (const float*)d_in[i]; break;
            case 2 * N_EDGES:       ei = d_in[i]; break;
            case IN_CH * HID_CH:    W1 = (const float*)d_in[i]; break;
            case HID_CH:            b1 = (const float*)d_in[i]; break;
            case HID_CH * OUT_CH:   W2 = (const float*)d_in[i]; break;
            case OUT_CH:            b2 = (const float*)d_in[i]; break;
            default: break;
        }
    }
    float* out = (float*)d_out;

    const int NC4 = N_NODES * OUT_CH / 4;
    const int SCAN_NB = (N_NODES + SCAN_BLK - 1) / SCAN_BLK;  // 196

    detect_dtype_kernel<<<1, 32>>>((const int*)ei);
    init_deg_kernel<<<(N_NODES + 255) / 256, 256>>>();
    deg_edges_kernel<<<(N_EDGES + 255) / 256, 256>>>(ei);

    // CSR build (selfc + degree histogram fused into scanA)
    scanA_kernel<<<SCAN_NB, SCAN_BLK>>>();
    scanB_kernel<<<1, 256>>>(SCAN_NB);
    scanC_kernel<<<(N_NODES + 255) / 256, 256>>>();
    scan_hist_kernel<<<1, MAXDEG>>>();
    perm_kernel<<<(N_NODES + 255) / 256, 256>>>();
    csr_fill_kernel<<<(N_EDGES + 255) / 256, 256>>>(ei);

    // W1 split (x is split in-kernel)
    split_w1t_kernel<<<(HID_CH * IN_CH + 255) / 256, 256>>>(W1);

    // fused MLP: h0 = relu(x@W1+b1)@W2 + b2   (tensor cores, split-bf16)
    init_h0_bias_kernel<<<(NC4 + 255) / 256, 256>>>(b2);
    {
        dim3 grid((N_NODES + 127) / 128, HID_CH / 128);
        mlp_mma_kernel<<<grid, 256>>>(x, b1, W2);
    }

    // propagation: 10 fused pull+combine steps
    const int PB = (int)(((size_t)N_NODES * 8 + 255) / 256);  // 3125

    pull_kernel<0, 1><<<PB, 256>>>(out); // k=0
    pull_kernel<1, 2><<<PB, 256>>>(out); // k=1
    pull_kernel<2, 1><<<PB, 256>>>(out); // k=2
    pull_kernel<1, 2><<<PB, 256>>>(out); // k=3
    pull_kernel<2, 1><<<PB, 256>>>(out); // k=4
    pull_kernel<1, 2><<<PB, 256>>>(out); // k=5
    pull_kernel<2, 1><<<PB, 256>>>(out); // k=6
    pull_kernel<1, 2><<<PB, 256>>>(out); // k=7
    pull_kernel<2, 1><<<PB, 256>>>(out); // k=8
    pull_kernel<1, 3><<<PB, 256>>>(out); // k=9 -> out
}

// round 10
// speedup vs baseline: 1.0365x; 1.0365x over previous
#include <cuda_runtime.h>
#include <cuda_bf16.h>
#include <cstdint>

// ---------------- problem constants ----------------
#define N_NODES 100000
#define IN_CH   512
#define HID_CH  256
#define OUT_CH  32
#define N_EDGES 1600000
#define K_STEPS 10
#define ALPHA   0.1f

// ---------------- device scratch (no allocations allowed) ----------------
__device__ float g_h0[(size_t)N_NODES * OUT_CH];
__device__ float g_ha[(size_t)N_NODES * OUT_CH];
__device__ float g_hb[(size_t)N_NODES * OUT_CH];
__device__ int   g_deg[N_NODES];
__device__ float g_selfc[N_NODES];
__device__ int   g_idx64;

// CSR (dst-sorted) for pull aggregation
__device__ int   g_rowptr[N_NODES + 1];
__device__ int   g_fill[N_NODES];
__device__ int   g_partial[256];
__device__ int2  g_csr[N_EDGES];       // {src, coef_bits}

// split-bf16 W1^T for the tensor-core GEMM ([n][k])
__device__ __align__(16) __nv_bfloat16 g_w1t_h[(size_t)HID_CH * IN_CH];
__device__ __align__(16) __nv_bfloat16 g_w1t_l[(size_t)HID_CH * IN_CH];

// ---------------- dtype detection ----------------
__global__ void detect_dtype_kernel(const int* __restrict__ ei32) {
    int t = threadIdx.x;
    int any = 0;
    for (int i = t; i < 1024; i += 32) any |= ei32[2 * i + 1];
#pragma unroll
    for (int o = 16; o; o >>= 1) any |= __shfl_xor_sync(0xffffffffu, any, o);
    if (t == 0) g_idx64 = (any == 0) ? 1 : 0;
}

__device__ __forceinline__ int load_idx(const void* ei, size_t pos, int is64) {
    long long v = is64 ? ((const long long*)ei)[pos] : (long long)((const int*)ei)[pos];
    if (v < 0) v = 0;
    if (v >= N_NODES) v = N_NODES - 1;
    return (int)v;
}

// ---------------- degree ----------------
__global__ void init_deg_kernel() {
    int i = blockIdx.x * blockDim.x + threadIdx.x;
    if (i < N_NODES) g_deg[i] = 1;  // self-loop
}

__global__ void deg_edges_kernel(const void* __restrict__ ei) {
    int e = blockIdx.x * blockDim.x + threadIdx.x;
    if (e >= N_EDGES) return;
    int is64 = g_idx64;
    atomicAdd(&g_deg[load_idx(ei, (size_t)N_EDGES + e, is64)], 1);
}

// ---------------- CSR build: warp-shuffle scans + fused fill ----------------
#define SCAN_BLK 512
__global__ void scanA_kernel() {   // exclusive scan of (deg-1) + selfc
    __shared__ int wsum[16];
    int t = threadIdx.x;
    int i = blockIdx.x * SCAN_BLK + t;
    int v = (i < N_NODES) ? (g_deg[i] - 1) : 0;
    if (i < N_NODES) g_selfc[i] = 1.0f / (float)(v + 1);
    int lane = t & 31, w = t >> 5;
    int s = v;  // inclusive warp scan
#pragma unroll
    for (int off = 1; off < 32; off <<= 1) {
        int x = __shfl_up_sync(0xffffffffu, s, off);
        if (lane >= off) s += x;
    }
    if (lane == 31) wsum[w] = s;
    __syncthreads();
    if (w == 0) {
        int ws = (lane < 16) ? wsum[lane] : 0;
#pragma unroll
        for (int off = 1; off < 16; off <<= 1) {
            int x = __shfl_up_sync(0xffffffffu, ws, off);
            if (lane >= off) ws += x;
        }
        if (lane < 16) wsum[lane] = ws;
    }
    __syncthreads();
    int incl = s + ((w > 0) ? wsum[w - 1] : 0);
    if (i < N_NODES) g_rowptr[i] = incl - v;   // exclusive within block
    if (t == SCAN_BLK - 1) g_partial[blockIdx.x] = incl;
}

__global__ void scanB_kernel(int nblocks) {    // 256-element warp-shuffle scan
    __shared__ int wsum[8];
    int t = threadIdx.x;
    int lane = t & 31, w = t >> 5;
    int v = (t < nblocks) ? g_partial[t] : 0;
    int s = v;
#pragma unroll
    for (int off = 1; off < 32; off <<= 1) {
        int x = __shfl_up_sync(0xffffffffu, s, off);
        if (lane >= off) s += x;
    }
    if (lane == 31) wsum[w] = s;
    __syncthreads();
    if (w == 0) {
        int ws = (lane < 8) ? wsum[lane] : 0;
#pragma unroll
        for (int off = 1; off < 8; off <<= 1) {
            int x = __shfl_up_sync(0xffffffffu, ws, off);
            if (lane >= off) ws += x;
        }
        if (lane < 8) wsum[lane] = ws;
    }
    __syncthreads();
    int incl = s + ((w > 0) ? wsum[w - 1] : 0);
    if (t < nblocks) g_partial[t] = incl - v;  // exclusive
}

__global__ void scanC_kernel() {               // add block offsets, zero fill
    int i = blockIdx.x * blockDim.x + threadIdx.x;
    if (i < N_NODES) {
        g_rowptr[i] += g_partial[i / SCAN_BLK];
        g_fill[i] = 0;
    }
    if (i == 0) g_rowptr[N_NODES] = N_EDGES;
}

// fused: read edge_index, compute coef, write CSR slot
__global__ void csr_fill_kernel(const void* __restrict__ ei) {
    int e = blockIdx.x * blockDim.x + threadIdx.x;
    if (e >= N_EDGES) return;
    int is64 = g_idx64;
    int s = load_idx(ei, e, is64);
    int d = load_idx(ei, (size_t)N_EDGES + e, is64);
    float c = rsqrtf((float)g_deg[s]) * rsqrtf((float)g_deg[d]);
    int pos = g_rowptr[d] + atomicAdd(&g_fill[d], 1);
    g_csr[pos] = make_int2(s, __float_as_int(c));
}

__global__ void init_h0_bias_kernel(const float* __restrict__ b2) {
    int i = blockIdx.x * blockDim.x + threadIdx.x;
    if (i < N_NODES * OUT_CH / 4) {
        const float4* b2v = (const float4*)b2;
        ((float4*)g_h0)[i] = b2v[i & 7];
    }
}

// ---------------- split-precision conversion ----------------
__device__ __forceinline__ void split1(float v, unsigned short& h, unsigned short& l) {
    __nv_bfloat16 hb = __float2bfloat16(v);
    float r = v - __bfloat162float(hb);
    __nv_bfloat16 lb = __float2bfloat16(r);
    h = *(unsigned short*)&hb;
    l = *(unsigned short*)&lb;
}

__global__ void split_w1t_kernel(const float* __restrict__ W1) {
    int i = blockIdx.x * blockDim.x + threadIdx.x;
    if (i >= HID_CH * IN_CH) return;
    int n = i >> 9;
    int k = i & 511;
    unsigned short h, l;
    split1(W1[(size_t)k * HID_CH + n], h, l);
    ((unsigned short*)g_w1t_h)[i] = h;
    ((unsigned short*)g_w1t_l)[i] = l;
}

// ---------------- tensor-core fused MLP ----------------
#define MMA_BF16(d, a, b0v, b1v)                                             \
    asm volatile(                                                            \
        "mma.sync.aligned.m16n8k16.row.col.f32.bf16.bf16.f32 "               \
        "{%0,%1,%2,%3}, {%4,%5,%6,%7}, {%8,%9}, {%0,%1,%2,%3};"              \
        : "+f"(d[0]), "+f"(d[1]), "+f"(d[2]), "+f"(d[3])                     \
        : "r"(a[0]), "r"(a[1]), "r"(a[2]), "r"(a[3]), "r"(b0v), "r"(b1v))

#define APITCH 40
#define CPITCH 68

__global__ __launch_bounds__(256)
void mlp_mma_kernel(const float* __restrict__ x,
                    const float* __restrict__ b1, const float* __restrict__ W2) {
    __shared__ __align__(16) union {
        struct {
            __nv_bfloat16 Ah[128 * APITCH], Al[128 * APITCH];
            __nv_bfloat16 Bh[128 * APITCH], Bl[128 * APITCH];
        } s1;
        struct { float Cs[128 * CPITCH]; float W2s[64 * 32]; } s2;
    } u;

    const int tid  = threadIdx.x;
    const int warp = tid >> 5;
    const int lane = tid & 31;
    const int wm = warp >> 1;
    const int wn = warp & 1;
    const int g  = lane >> 2;
    const int t  = lane & 3;
    const int brow = blockIdx.x * 128;
    const int bcol = blockIdx.y * 128;

    float acc[2][8][4];
#pragma unroll
    for (int i = 0; i < 2; i++)
#pragma unroll
        for (int j = 0; j < 8; j++)
#pragma unroll
            for (int r = 0; r < 4; r++) acc[i][j][r] = 0.0f;

    float4 pa[4];
    uint4  pbh[2], pbl[2];

    auto load_tile = [&](int k0) {
#pragma unroll
        for (int l = 0; l < 4; l++) {
            int idx = tid + l * 256;
            int row = idx >> 3;
            int seg = idx & 7;
            if (brow + row < N_NODES)
                pa[l] = *(const float4*)&x[(size_t)(brow + row) * IN_CH + k0 + seg * 4];
            else
                pa[l] = make_float4(0.f, 0.f, 0.f, 0.f);
        }
#pragma unroll
        for (int l = 0; l < 2; l++) {
            int idx = tid + l * 256;
            int row = idx >> 2;
            int seg = idx & 3;
            size_t go = (size_t)(bcol + row) * IN_CH + k0 + seg * 8;
            pbh[l] = *(const uint4*)&g_w1t_h[go];
            pbl[l] = *(const uint4*)&g_w1t_l[go];
        }
    };

    auto store_tile = [&]() {
#pragma unroll
        for (int l = 0; l < 4; l++) {
            int idx = tid + l * 256;
            int row = idx >> 3;
            int seg = idx & 7;
            ushort4 hh, ll;
            split1(pa[l].x, hh.x, ll.x);
            split1(pa[l].y, hh.y, ll.y);
            split1(pa[l].z, hh.z, ll.z);
            split1(pa[l].w, hh.w, ll.w);
            *(ushort4*)&u.s1.Ah[row * APITCH + seg * 4] = hh;
            *(ushort4*)&u.s1.Al[row * APITCH + seg * 4] = ll;
        }
#pragma unroll
        for (int l = 0; l < 2; l++) {
            int idx = tid + l * 256;
            int row = idx >> 2;
            int seg = idx & 3;
            *(uint4*)&u.s1.Bh[row * APITCH + seg * 8] = pbh[l];
            *(uint4*)&u.s1.Bl[row * APITCH + seg * 8] = pbl[l];
        }
    };

    load_tile(0);
    store_tile();
    __syncthreads();

    for (int k0 = 0; k0 < IN_CH; k0 += 32) {
        const bool more = (k0 + 32) < IN_CH;
        if (more) load_tile(k0 + 32);

#pragma unroll
        for (int kk = 0; kk < 32; kk += 16) {
            uint32_t ah[2][4], al[2][4];
#pragma unroll
            for (int i = 0; i < 2; i++) {
                int r = wm * 32 + i * 16 + g;
                int base = r * APITCH + kk + t * 2;
                ah[i][0] = *(const uint32_t*)&u.s1.Ah[base];
                ah[i][1] = *(const uint32_t*)&u.s1.Ah[base + 8 * APITCH];
                ah[i][2] = *(const uint32_t*)&u.s1.Ah[base + 8];
                ah[i][3] = *(const uint32_t*)&u.s1.Ah[base + 8 * APITCH + 8];
                al[i][0] = *(const uint32_t*)&u.s1.Al[base];
                al[i][1] = *(const uint32_t*)&u.s1.Al[base + 8 * APITCH];
                al[i][2] = *(const uint32_t*)&u.s1.Al[base + 8];
                al[i][3] = *(const uint32_t*)&u.s1.Al[base + 8 * APITCH + 8];
            }
#pragma unroll
            for (int j = 0; j < 8; j++) {
                int n = wn * 64 + j * 8 + g;
                int bb = n * APITCH + kk + t * 2;
                uint32_t bh0 = *(const uint32_t*)&u.s1.Bh[bb];
                uint32_t bh1 = *(const uint32_t*)&u.s1.Bh[bb + 8];
                uint32_t bl0 = *(const uint32_t*)&u.s1.Bl[bb];
                uint32_t bl1 = *(const uint32_t*)&u.s1.Bl[bb + 8];
#pragma unroll
                for (int i = 0; i < 2; i++) {
                    MMA_BF16(acc[i][j], ah[i], bh0, bh1);
                    MMA_BF16(acc[i][j], ah[i], bl0, bl1);
                    MMA_BF16(acc[i][j], al[i], bh0, bh1);
                }
            }
        }
        __syncthreads();
        if (more) {
            store_tile();
            __syncthreads();
        }
    }

    // ---- stage 2: relu(acc + b1) @ W2-slice, two 64-col halves ----
    const int c    = tid & 31;
    const int rgrp = tid >> 5;
    float sum[16];
#pragma unroll
    for (int rr = 0; rr < 16; rr++) sum[rr] = 0.0f;

#pragma unroll
    for (int h = 0; h < 2; h++) {
        __syncthreads();
        if (wn == h) {
#pragma unroll
            for (int i = 0; i < 2; i++)
#pragma unroll
                for (int j = 0; j < 8; j++) {
                    int row = wm * 32 + i * 16 + g;
                    int col = j * 8 + t * 2;
                    float bias0 = b1[bcol + h * 64 + col];
                    float bias1 = b1[bcol + h * 64 + col + 1];
                    float2 v0, v1;
                    v0.x = fmaxf(acc[i][j][0] + bias0, 0.0f);
                    v0.y = fmaxf(acc[i][j][1] + bias1, 0.0f);
                    v1.x = fmaxf(acc[i][j][2] + bias0, 0.0f);
                    v1.y = fmaxf(acc[i][j][3] + bias1, 0.0f);
                    *(float2*)&u.s2.Cs[row * CPITCH + col]       = v0;
                    *(float2*)&u.s2.Cs[(row + 8) * CPITCH + col] = v1;
                }
        }
#pragma unroll
        for (int l = 0; l < 8; l++) {
            int q = tid + l * 256;
            u.s2.W2s[q] = W2[(size_t)(bcol + h * 64 + (q >> 5)) * OUT_CH + (q & 31)];
        }
        __syncthreads();

#pragma unroll
        for (int k4 = 0; k4 < 16; k4++) {
            float w0 = u.s2.W2s[(k4 * 4 + 0) * 32 + c];
            float w1 = u.s2.W2s[(k4 * 4 + 1) * 32 + c];
            float w2 = u.s2.W2s[(k4 * 4 + 2) * 32 + c];
            float w3 = u.s2.W2s[(k4 * 4 + 3) * 32 + c];
#pragma unroll
            for (int rr = 0; rr < 16; rr++) {
                float4 cv = *(const float4*)&u.s2.Cs[(rgrp * 16 + rr) * CPITCH + k4 * 4];
                sum[rr] += cv.x * w0 + cv.y * w1 + cv.z * w2 + cv.w * w3;
            }
        }
    }

#pragma unroll
    for (int rr = 0; rr < 16; rr++) {
        int grow = brow + rgrp * 16 + rr;
        if (grow < N_NODES)
            atomicAdd(&g_h0[(size_t)grow * OUT_CH + c], sum[rr]);
    }
}

// ---------------- APPNP propagation: fused pull + combine ----------------
template <int SEL>
__device__ __forceinline__ const float* buf_const() {
    return SEL == 0 ? g_h0 : (SEL == 1 ? g_ha : g_hb);
}

// 8 lanes per node; lane q handles channels [4q, 4q+4).
template <int CUR, int NXT>
__global__ void pull_kernel(float* __restrict__ out) {
    const float* __restrict__ h = buf_const<CUR>();
    float* __restrict__ h_next =
        (NXT == 3) ? out : (NXT == 1 ? g_ha : g_hb);
    int t = blockIdx.x * blockDim.x + threadIdx.x;
    int node = t >> 3;
    int q = t & 7;
    if (node >= N_NODES) return;

    int beg = g_rowptr[node];
    int end = g_rowptr[node + 1];

    float4 acc = make_float4(0.f, 0.f, 0.f, 0.f);
#pragma unroll 4
    for (int i = beg; i < end; i++) {
        int2 ed = __ldg(&g_csr[i]);
        float cf = __int_as_float(ed.y);
        float4 hv = *(const float4*)&h[(size_t)ed.x * OUT_CH + q * 4];
        acc.x += cf * hv.x;
        acc.y += cf * hv.y;
        acc.z += cf * hv.z;
        acc.w += cf * hv.w;
    }

    size_t i4 = (size_t)node * 8 + q;
    float sc = g_selfc[node];
    float4 hc = ((const float4*)h)[i4];
    float4 h0v = ((const float4*)g_h0)[i4];
    float4 r;
    r.x = ALPHA * h0v.x + (1.0f - ALPHA) * (acc.x + sc * hc.x);
    r.y = ALPHA * h0v.y + (1.0f - ALPHA) * (acc.y + sc * hc.y);
    r.z = ALPHA * h0v.z + (1.0f - ALPHA) * (acc.z + sc * hc.z);
    r.w = ALPHA * h0v.w + (1.0f - ALPHA) * (acc.w + sc * hc.w);
    ((float4*)h_next)[i4] = r;
}

// ---------------- host launch ----------------
extern "C" void kernel_launch(void* const* d_in, const int* in_sizes, int n_in,
                              void* d_out, int out_size) {
    const float* x = nullptr;  const void* ei = nullptr;
    const float* W1 = nullptr; const float* b1 = nullptr;
    const float* W2 = nullptr; const float* b2 = nullptr;
    for (int i = 0; i < n_in; i++) {
        switch (in_sizes[i]) {
            case N_NODES * IN_CH:   x  = (const float*)d_in[i]; break;
            case 2 * N_EDGES:       ei = d_in[i]; break;
            case IN_CH * HID_CH:    W1 = (const float*)d_in[i]; break;
            case HID_CH:            b1 = (const float*)d_in[i]; break;
            case HID_CH * OUT_CH:   W2 = (const float*)d_in[i]; break;
            case OUT_CH:            b2 = (const float*)d_in[i]; break;
            default: break;
        }
    }
    float* out = (float*)d_out;

    const int NC4 = N_NODES * OUT_CH / 4;
    const int SCAN_NB = (N_NODES + SCAN_BLK - 1) / SCAN_BLK;  // 196

    detect_dtype_kernel<<<1, 32>>>((const int*)ei);
    init_deg_kernel<<<(N_NODES + 255) / 256, 256>>>();
    deg_edges_kernel<<<(N_EDGES + 255) / 256, 256>>>(ei);

    // CSR build (selfc fused into scanA; warp-shuffle scans)
    scanA_kernel<<<SCAN_NB, SCAN_BLK>>>();
    scanB_kernel<<<1, 256>>>(SCAN_NB);
    scanC_kernel<<<(N_NODES + 255) / 256, 256>>>();
    csr_fill_kernel<<<(N_EDGES + 255) / 256, 256>>>(ei);

    // W1 split (x is split in-kernel)
    split_w1t_kernel<<<(HID_CH * IN_CH + 255) / 256, 256>>>(W1);

    // fused MLP: h0 = relu(x@W1+b1)@W2 + b2   (tensor cores, split-bf16)
    init_h0_bias_kernel<<<(NC4 + 255) / 256, 256>>>(b2);
    {
        dim3 grid((N_NODES + 127) / 128, HID_CH / 128);
        mlp_mma_kernel<<<grid, 256>>>(x, b1, W2);
    }

    // propagation: 10 fused pull+combine steps
    const int PB = (int)(((size_t)N_NODES * 8 + 255) / 256);  // 3125

    pull_kernel<0, 1><<<PB, 256>>>(out); // k=0
    pull_kernel<1, 2><<<PB, 256>>>(out); // k=1
    pull_kernel<2, 1><<<PB, 256>>>(out); // k=2
    pull_kernel<1, 2><<<PB, 256>>>(out); // k=3
    pull_kernel<2, 1><<<PB, 256>>>(out); // k=4
    pull_kernel<1, 2><<<PB, 256>>>(out); // k=5
    pull_kernel<2, 1><<<PB, 256>>>(out); // k=6
    pull_kernel<1, 2><<<PB, 256>>>(out); // k=7
    pull_kernel<2, 1><<<PB, 256>>>(out); // k=8
    pull_kernel<1, 3><<<PB, 256>>>(out); // k=9 -> out
}

// round 12
// speedup vs baseline: 1.0811x; 1.0430x over previous
#include <cuda_runtime.h>
#include <cuda_bf16.h>
#include <cstdint>

// ---------------- problem constants ----------------
#define N_NODES 100000
#define IN_CH   512
#define HID_CH  256
#define OUT_CH  32
#define N_EDGES 1600000
#define K_STEPS 10
#define ALPHA   0.1f

// ---------------- device scratch (no allocations allowed) ----------------
__device__ float g_h0[(size_t)N_NODES * OUT_CH];
__device__ float g_ha[(size_t)N_NODES * OUT_CH];
__device__ float g_hb[(size_t)N_NODES * OUT_CH];
__device__ int   g_deg[N_NODES];
__device__ float g_selfc[N_NODES];
__device__ int   g_idx64;

// CSR (dst-sorted) for pull aggregation
__device__ int   g_rowptr[N_NODES + 1];
__device__ int   g_fill[N_NODES];
__device__ int   g_partial[256];
__device__ int2  g_csr[N_EDGES];       // {src, coef_bits}

// split-bf16 W1^T for the tensor-core GEMM ([n][k])
__device__ __align__(16) __nv_bfloat16 g_w1t_h[(size_t)HID_CH * IN_CH];
__device__ __align__(16) __nv_bfloat16 g_w1t_l[(size_t)HID_CH * IN_CH];

// ---------------- dtype detection ----------------
__global__ void detect_dtype_kernel(const int* __restrict__ ei32) {
    int t = threadIdx.x;
    int any = 0;
    for (int i = t; i < 1024; i += 32) any |= ei32[2 * i + 1];
#pragma unroll
    for (int o = 16; o; o >>= 1) any |= __shfl_xor_sync(0xffffffffu, any, o);
    if (t == 0) g_idx64 = (any == 0) ? 1 : 0;
}

__device__ __forceinline__ int load_idx(const void* ei, size_t pos, int is64) {
    long long v = is64 ? ((const long long*)ei)[pos] : (long long)((const int*)ei)[pos];
    if (v < 0) v = 0;
    if (v >= N_NODES) v = N_NODES - 1;
    return (int)v;
}

// ---------------- degree ----------------
__global__ void init_deg_kernel() {
    int i = blockIdx.x * blockDim.x + threadIdx.x;
    if (i < N_NODES) g_deg[i] = 1;  // self-loop
}

__global__ void deg_edges_kernel(const void* __restrict__ ei) {
    int e = blockIdx.x * blockDim.x + threadIdx.x;
    if (e >= N_EDGES) return;
    int is64 = g_idx64;
    atomicAdd(&g_deg[load_idx(ei, (size_t)N_EDGES + e, is64)], 1);
}

// ---------------- CSR build: warp-shuffle scans + fused fill ----------------
#define SCAN_BLK 512
__global__ void scanA_kernel() {   // exclusive scan of (deg-1) + selfc
    __shared__ int wsum[16];
    int t = threadIdx.x;
    int i = blockIdx.x * SCAN_BLK + t;
    int v = (i < N_NODES) ? (g_deg[i] - 1) : 0;
    if (i < N_NODES) g_selfc[i] = 1.0f / (float)(v + 1);
    int lane = t & 31, w = t >> 5;
    int s = v;
#pragma unroll
    for (int off = 1; off < 32; off <<= 1) {
        int x = __shfl_up_sync(0xffffffffu, s, off);
        if (lane >= off) s += x;
    }
    if (lane == 31) wsum[w] = s;
    __syncthreads();
    if (w == 0) {
        int ws = (lane < 16) ? wsum[lane] : 0;
#pragma unroll
        for (int off = 1; off < 16; off <<= 1) {
            int x = __shfl_up_sync(0xffffffffu, ws, off);
            if (lane >= off) ws += x;
        }
        if (lane < 16) wsum[lane] = ws;
    }
    __syncthreads();
    int incl = s + ((w > 0) ? wsum[w - 1] : 0);
    if (i < N_NODES) g_rowptr[i] = incl - v;
    if (t == SCAN_BLK - 1) g_partial[blockIdx.x] = incl;
}

__global__ void scanB_kernel(int nblocks) {
    __shared__ int wsum[8];
    int t = threadIdx.x;
    int lane = t & 31, w = t >> 5;
    int v = (t < nblocks) ? g_partial[t] : 0;
    int s = v;
#pragma unroll
    for (int off = 1; off < 32; off <<= 1) {
        int x = __shfl_up_sync(0xffffffffu, s, off);
        if (lane >= off) s += x;
    }
    if (lane == 31) wsum[w] = s;
    __syncthreads();
    if (w == 0) {
        int ws = (lane < 8) ? wsum[lane] : 0;
#pragma unroll
        for (int off = 1; off < 8; off <<= 1) {
            int x = __shfl_up_sync(0xffffffffu, ws, off);
            if (lane >= off) ws += x;
        }
        if (lane < 8) wsum[lane] = ws;
    }
    __syncthreads();
    int incl = s + ((w > 0) ? wsum[w - 1] : 0);
    if (t < nblocks) g_partial[t] = incl - v;
}

__global__ void scanC_kernel() {
    int i = blockIdx.x * blockDim.x + threadIdx.x;
    if (i < N_NODES) {
        g_rowptr[i] += g_partial[i / SCAN_BLK];
        g_fill[i] = 0;
    }
    if (i == 0) g_rowptr[N_NODES] = N_EDGES;
}

__global__ void csr_fill_kernel(const void* __restrict__ ei) {
    int e = blockIdx.x * blockDim.x + threadIdx.x;
    if (e >= N_EDGES) return;
    int is64 = g_idx64;
    int s = load_idx(ei, e, is64);
    int d = load_idx(ei, (size_t)N_EDGES + e, is64);
    float c = rsqrtf((float)g_deg[s]) * rsqrtf((float)g_deg[d]);
    int pos = g_rowptr[d] + atomicAdd(&g_fill[d], 1);
    g_csr[pos] = make_int2(s, __float_as_int(c));
}

__global__ void init_h0_bias_kernel(const float* __restrict__ b2) {
    int i = blockIdx.x * blockDim.x + threadIdx.x;
    if (i < N_NODES * OUT_CH / 4) {
        const float4* b2v = (const float4*)b2;
        ((float4*)g_h0)[i] = b2v[i & 7];
    }
}

// ---------------- split-precision conversion ----------------
__device__ __forceinline__ void split1(float v, unsigned short& h, unsigned short& l) {
    __nv_bfloat16 hb = __float2bfloat16(v);
    float r = v - __bfloat162float(hb);
    __nv_bfloat16 lb = __float2bfloat16(r);
    h = *(unsigned short*)&hb;
    l = *(unsigned short*)&lb;
}

__global__ void split_w1t_kernel(const float* __restrict__ W1) {
    int i = blockIdx.x * blockDim.x + threadIdx.x;
    if (i >= HID_CH * IN_CH) return;
    int n = i >> 9;
    int k = i & 511;
    unsigned short h, l;
    split1(W1[(size_t)k * HID_CH + n], h, l);
    ((unsigned short*)g_w1t_h)[i] = h;
    ((unsigned short*)g_w1t_l)[i] = l;
}

// ---------------- tensor-core fused MLP (mma.sync, split-bf16) ----------------
#define MMA_BF16(d, a, b0v, b1v)                                             \
    asm volatile(                                                            \
        "mma.sync.aligned.m16n8k16.row.col.f32.bf16.bf16.f32 "               \
        "{%0,%1,%2,%3}, {%4,%5,%6,%7}, {%8,%9}, {%0,%1,%2,%3};"              \
        : "+f"(d[0]), "+f"(d[1]), "+f"(d[2]), "+f"(d[3])                     \
        : "r"(a[0]), "r"(a[1]), "r"(a[2]), "r"(a[3]), "r"(b0v), "r"(b1v))

#define APITCH 40
#define CPITCH 68

__global__ __launch_bounds__(256)
void mlp_mma_kernel(const float* __restrict__ x,
                    const float* __restrict__ b1, const float* __restrict__ W2) {
    __shared__ __align__(16) union {
        struct {
            __nv_bfloat16 Ah[128 * APITCH], Al[128 * APITCH];
            __nv_bfloat16 Bh[128 * APITCH], Bl[128 * APITCH];
        } s1;
        struct { float Cs[128 * CPITCH]; float W2s[64 * 32]; } s2;
    } u;

    const int tid  = threadIdx.x;
    const int warp = tid >> 5;
    const int lane = tid & 31;
    const int wm = warp >> 1;
    const int wn = warp & 1;
    const int g  = lane >> 2;
    const int t  = lane & 3;
    const int brow = blockIdx.x * 128;
    const int bcol = blockIdx.y * 128;

    float acc[2][8][4];
#pragma unroll
    for (int i = 0; i < 2; i++)
#pragma unroll
        for (int j = 0; j < 8; j++)
#pragma unroll
            for (int r = 0; r < 4; r++) acc[i][j][r] = 0.0f;

    float4 pa[4];
    uint4  pbh[2], pbl[2];

    auto load_tile = [&](int k0) {
#pragma unroll
        for (int l = 0; l < 4; l++) {
            int idx = tid + l * 256;
            int row = idx >> 3;
            int seg = idx & 7;
            if (brow + row < N_NODES)
                pa[l] = *(const float4*)&x[(size_t)(brow + row) * IN_CH + k0 + seg * 4];
            else
                pa[l] = make_float4(0.f, 0.f, 0.f, 0.f);
        }
#pragma unroll
        for (int l = 0; l < 2; l++) {
            int idx = tid + l * 256;
            int row = idx >> 2;
            int seg = idx & 3;
            size_t go = (size_t)(bcol + row) * IN_CH + k0 + seg * 8;
            pbh[l] = *(const uint4*)&g_w1t_h[go];
            pbl[l] = *(const uint4*)&g_w1t_l[go];
        }
    };

    auto store_tile = [&]() {
#pragma unroll
        for (int l = 0; l < 4; l++) {
            int idx = tid + l * 256;
            int row = idx >> 3;
            int seg = idx & 7;
            ushort4 hh, ll;
            split1(pa[l].x, hh.x, ll.x);
            split1(pa[l].y, hh.y, ll.y);
            split1(pa[l].z, hh.z, ll.z);
            split1(pa[l].w, hh.w, ll.w);
            *(ushort4*)&u.s1.Ah[row * APITCH + seg * 4] = hh;
            *(ushort4*)&u.s1.Al[row * APITCH + seg * 4] = ll;
        }
#pragma unroll
        for (int l = 0; l < 2; l++) {
            int idx = tid + l * 256;
            int row = idx >> 2;
            int seg = idx & 3;
            *(uint4*)&u.s1.Bh[row * APITCH + seg * 8] = pbh[l];
            *(uint4*)&u.s1.Bl[row * APITCH + seg * 8] = pbl[l];
        }
    };

    load_tile(0);
    store_tile();
    __syncthreads();

    for (int k0 = 0; k0 < IN_CH; k0 += 32) {
        const bool more = (k0 + 32) < IN_CH;
        if (more) load_tile(k0 + 32);

#pragma unroll
        for (int kk = 0; kk < 32; kk += 16) {
            uint32_t ah[2][4], al[2][4];
#pragma unroll
            for (int i = 0; i < 2; i++) {
                int r = wm * 32 + i * 16 + g;
                int base = r * APITCH + kk + t * 2;
                ah[i][0] = *(const uint32_t*)&u.s1.Ah[base];
                ah[i][1] = *(const uint32_t*)&u.s1.Ah[base + 8 * APITCH];
                ah[i][2] = *(const uint32_t*)&u.s1.Ah[base + 8];
                ah[i][3] = *(const uint32_t*)&u.s1.Ah[base + 8 * APITCH + 8];
                al[i][0] = *(const uint32_t*)&u.s1.Al[base];
                al[i][1] = *(const uint32_t*)&u.s1.Al[base + 8 * APITCH];
                al[i][2] = *(const uint32_t*)&u.s1.Al[base + 8];
                al[i][3] = *(const uint32_t*)&u.s1.Al[base + 8 * APITCH + 8];
            }
#pragma unroll
            for (int j = 0; j < 8; j++) {
                int n = wn * 64 + j * 8 + g;
                int bb = n * APITCH + kk + t * 2;
                uint32_t bh0 = *(const uint32_t*)&u.s1.Bh[bb];
                uint32_t bh1 = *(const uint32_t*)&u.s1.Bh[bb + 8];
                uint32_t bl0 = *(const uint32_t*)&u.s1.Bl[bb];
                uint32_t bl1 = *(const uint32_t*)&u.s1.Bl[bb + 8];
#pragma unroll
                for (int i = 0; i < 2; i++) {
                    MMA_BF16(acc[i][j], ah[i], bh0, bh1);
                    MMA_BF16(acc[i][j], ah[i], bl0, bl1);
                    MMA_BF16(acc[i][j], al[i], bh0, bh1);
                }
            }
        }
        __syncthreads();
        if (more) {
            store_tile();
            __syncthreads();
        }
    }

    // ---- stage 2: relu(acc + b1) @ W2-slice, two 64-col halves ----
    const int c    = tid & 31;
    const int rgrp = tid >> 5;
    float sum[16];
#pragma unroll
    for (int rr = 0; rr < 16; rr++) sum[rr] = 0.0f;

#pragma unroll
    for (int h = 0; h < 2; h++) {
        __syncthreads();
        if (wn == h) {
#pragma unroll
            for (int i = 0; i < 2; i++)
#pragma unroll
                for (int j = 0; j < 8; j++) {
                    int row = wm * 32 + i * 16 + g;
                    int col = j * 8 + t * 2;
                    float bias0 = b1[bcol + h * 64 + col];
                    float bias1 = b1[bcol + h * 64 + col + 1];
                    float2 v0, v1;
                    v0.x = fmaxf(acc[i][j][0] + bias0, 0.0f);
                    v0.y = fmaxf(acc[i][j][1] + bias1, 0.0f);
                    v1.x = fmaxf(acc[i][j][2] + bias0, 0.0f);
                    v1.y = fmaxf(acc[i][j][3] + bias1, 0.0f);
                    *(float2*)&u.s2.Cs[row * CPITCH + col]       = v0;
                    *(float2*)&u.s2.Cs[(row + 8) * CPITCH + col] = v1;
                }
        }
#pragma unroll
        for (int l = 0; l < 8; l++) {
            int q = tid + l * 256;
            u.s2.W2s[q] = W2[(size_t)(bcol + h * 64 + (q >> 5)) * OUT_CH + (q & 31)];
        }
        __syncthreads();

#pragma unroll
        for (int k4 = 0; k4 < 16; k4++) {
            float w0 = u.s2.W2s[(k4 * 4 + 0) * 32 + c];
            float w1 = u.s2.W2s[(k4 * 4 + 1) * 32 + c];
            float w2 = u.s2.W2s[(k4 * 4 + 2) * 32 + c];
            float w3 = u.s2.W2s[(k4 * 4 + 3) * 32 + c];
#pragma unroll
            for (int rr = 0; rr < 16; rr++) {
                float4 cv = *(const float4*)&u.s2.Cs[(rgrp * 16 + rr) * CPITCH + k4 * 4];
                sum[rr] += cv.x * w0 + cv.y * w1 + cv.z * w2 + cv.w * w3;
            }
        }
    }

#pragma unroll
    for (int rr = 0; rr < 16; rr++) {
        int grow = brow + rgrp * 16 + rr;
        if (grow < N_NODES)
            atomicAdd(&g_h0[(size_t)grow * OUT_CH + c], sum[rr]);
    }
}

// ---------------- APPNP propagation: fused pull + combine ----------------
template <int SEL>
__device__ __forceinline__ const float* buf_const() {
    return SEL == 0 ? g_h0 : (SEL == 1 ? g_ha : g_hb);
}

template <int CUR, int NXT>
__global__ void pull_kernel(float* __restrict__ out) {
    const float* __restrict__ h = buf_const<CUR>();
    float* __restrict__ h_next =
        (NXT == 3) ? out : (NXT == 1 ? g_ha : g_hb);
    int t = blockIdx.x * blockDim.x + threadIdx.x;
    int node = t >> 3;
    int q = t & 7;
    if (node >= N_NODES) return;

    int beg = g_rowptr[node];
    int end = g_rowptr[node + 1];

    float4 acc = make_float4(0.f, 0.f, 0.f, 0.f);
#pragma unroll 4
    for (int i = beg; i < end; i++) {
        int2 ed = __ldg(&g_csr[i]);
        float cf = __int_as_float(ed.y);
        float4 hv = *(const float4*)&h[(size_t)ed.x * OUT_CH + q * 4];
        acc.x += cf * hv.x;
        acc.y += cf * hv.y;
        acc.z += cf * hv.z;
        acc.w += cf * hv.w;
    }

    size_t i4 = (size_t)node * 8 + q;
    float sc = g_selfc[node];
    float4 hc = ((const float4*)h)[i4];
    float4 h0v = ((const float4*)g_h0)[i4];
    float4 r;
    r.x = ALPHA * h0v.x + (1.0f - ALPHA) * (acc.x + sc * hc.x);
    r.y = ALPHA * h0v.y + (1.0f - ALPHA) * (acc.y + sc * hc.y);
    r.z = ALPHA * h0v.z + (1.0f - ALPHA) * (acc.z + sc * hc.z);
    r.w = ALPHA * h0v.w + (1.0f - ALPHA) * (acc.w + sc * hc.w);
    ((float4*)h_next)[i4] = r;
}

// ---------------- host launch ----------------
extern "C" void kernel_launch(void* const* d_in, const int* in_sizes, int n_in,
                              void* d_out, int out_size) {
    const float* x = nullptr;  const void* ei = nullptr;
    const float* W1 = nullptr; const float* b1 = nullptr;
    const float* W2 = nullptr; const float* b2 = nullptr;
    for (int i = 0; i < n_in; i++) {
        switch (in_sizes[i]) {
            case N_NODES * IN_CH:   x  = (const float*)d_in[i]; break;
            case 2 * N_EDGES:       ei = d_in[i]; break;
            case IN_CH * HID_CH:    W1 = (const float*)d_in[i]; break;
            case HID_CH:            b1 = (const float*)d_in[i]; break;
            case HID_CH * OUT_CH:   W2 = (const float*)d_in[i]; break;
            case OUT_CH:            b2 = (const float*)d_in[i]; break;
            default: break;
        }
    }
    float* out = (float*)d_out;

    const int NC4 = N_NODES * OUT_CH / 4;
    const int SCAN_NB = (N_NODES + SCAN_BLK - 1) / SCAN_BLK;  // 196

    // One-time stream/event creation (no device memory involved; the captured
    // graph is identical on every call).
    static cudaStream_t s2 = [] {
        cudaStream_t s;
        cudaStreamCreateWithFlags(&s, cudaStreamNonBlocking);
        return s;
    }();
    static cudaEvent_t evF = [] {
        cudaEvent_t e;
        cudaEventCreateWithFlags(&e, cudaEventDisableTiming);
        return e;
    }();
    static cudaEvent_t evJ = [] {
        cudaEvent_t e;
        cudaEventCreateWithFlags(&e, cudaEventDisableTiming);
        return e;
    }();

    // ---- fork: branch B (MLP chain) on s2, branch A (CSR chain) on default ----
    cudaEventRecord(evF, 0);
    cudaStreamWaitEvent(s2, evF, 0);

    // branch B: split W1, init h0 with bias, fused MLP (independent of edges)
    split_w1t_kernel<<<(HID_CH * IN_CH + 255) / 256, 256, 0, s2>>>(W1);
    init_h0_bias_kernel<<<(NC4 + 255) / 256, 256, 0, s2>>>(b2);
    {
        dim3 grid((N_NODES + 127) / 128, HID_CH / 128);
        mlp_mma_kernel<<<grid, 256, 0, s2>>>(x, b1, W2);
    }
    cudaEventRecord(evJ, s2);

    // branch A: edge dtype + degrees + CSR build (independent of x/W)
    detect_dtype_kernel<<<1, 32>>>((const int*)ei);
    init_deg_kernel<<<(N_NODES + 255) / 256, 256>>>();
    deg_edges_kernel<<<(N_EDGES + 255) / 256, 256>>>(ei);
    scanA_kernel<<<SCAN_NB, SCAN_BLK>>>();
    scanB_kernel<<<1, 256>>>(SCAN_NB);
    scanC_kernel<<<(N_NODES + 255) / 256, 256>>>();
    csr_fill_kernel<<<(N_EDGES + 255) / 256, 256>>>(ei);

    // ---- join ----
    cudaStreamWaitEvent(0, evJ, 0);

    // propagation: 10 fused pull+combine steps
    const int PB = (int)(((size_t)N_NODES * 8 + 255) / 256);  // 3125

    pull_kernel<0, 1><<<PB, 256>>>(out); // k=0
    pull_kernel<1, 2><<<PB, 256>>>(out); // k=1
    pull_kernel<2, 1><<<PB, 256>>>(out); // k=2
    pull_kernel<1, 2><<<PB, 256>>>(out); // k=3
    pull_kernel<2, 1><<<PB, 256>>>(out); // k=4
    pull_kernel<1, 2><<<PB, 256>>>(out); // k=5
    pull_kernel<2, 1><<<PB, 256>>>(out); // k=6
    pull_kernel<1, 2><<<PB, 256>>>(out); // k=7
    pull_kernel<2, 1><<<PB, 256>>>(out); // k=8
    pull_kernel<1, 3><<<PB, 256>>>(out); // k=9 -> out
}

// round 13
// speedup vs baseline: 1.1119x; 1.0285x over previous
#include <cuda_runtime.h>
#include <cuda_bf16.h>
#include <cuda_fp16.h>
#include <cstdint>

// ---------------- problem constants ----------------
#define N_NODES 100000
#define IN_CH   512
#define HID_CH  256
#define OUT_CH  32
#define N_EDGES 1600000
#define K_STEPS 10
#define ALPHA   0.1f

// ---------------- device scratch (no allocations allowed) ----------------
__device__ float g_h0[(size_t)N_NODES * OUT_CH];
__device__ __align__(16) __half g_ha16[(size_t)N_NODES * OUT_CH];  // ping (fp16)
__device__ __align__(16) __half g_hb16[(size_t)N_NODES * OUT_CH];  // pong (fp16)
__device__ int   g_deg[N_NODES];
__device__ float g_selfc[N_NODES];
__device__ int   g_idx64;

// CSR (dst-sorted) for pull aggregation
__device__ int   g_rowptr[N_NODES + 1];
__device__ int   g_fill[N_NODES];
__device__ int   g_partial[256];
__device__ int2  g_csr[N_EDGES];       // {src, coef_bits}

// split-bf16 W1^T for the tensor-core GEMM ([n][k])
__device__ __align__(16) __nv_bfloat16 g_w1t_h[(size_t)HID_CH * IN_CH];
__device__ __align__(16) __nv_bfloat16 g_w1t_l[(size_t)HID_CH * IN_CH];

// ---------------- dtype detection ----------------
__global__ void detect_dtype_kernel(const int* __restrict__ ei32) {
    int t = threadIdx.x;
    int any = 0;
    for (int i = t; i < 1024; i += 32) any |= ei32[2 * i + 1];
#pragma unroll
    for (int o = 16; o; o >>= 1) any |= __shfl_xor_sync(0xffffffffu, any, o);
    if (t == 0) g_idx64 = (any == 0) ? 1 : 0;
}

__device__ __forceinline__ int load_idx(const void* ei, size_t pos, int is64) {
    long long v = is64 ? ((const long long*)ei)[pos] : (long long)((const int*)ei)[pos];
    if (v < 0) v = 0;
    if (v >= N_NODES) v = N_NODES - 1;
    return (int)v;
}

// ---------------- degree ----------------
__global__ void init_deg_kernel() {
    int i = blockIdx.x * blockDim.x + threadIdx.x;
    if (i < N_NODES) g_deg[i] = 1;  // self-loop
}

__global__ void deg_edges_kernel(const void* __restrict__ ei) {
    int e = blockIdx.x * blockDim.x + threadIdx.x;
    if (e >= N_EDGES) return;
    int is64 = g_idx64;
    atomicAdd(&g_deg[load_idx(ei, (size_t)N_EDGES + e, is64)], 1);
}

// ---------------- CSR build: warp-shuffle scans + fused fill ----------------
#define SCAN_BLK 512
__global__ void scanA_kernel() {   // exclusive scan of (deg-1) + selfc
    __shared__ int wsum[16];
    int t = threadIdx.x;
    int i = blockIdx.x * SCAN_BLK + t;
    int v = (i < N_NODES) ? (g_deg[i] - 1) : 0;
    if (i < N_NODES) g_selfc[i] = 1.0f / (float)(v + 1);
    int lane = t & 31, w = t >> 5;
    int s = v;
#pragma unroll
    for (int off = 1; off < 32; off <<= 1) {
        int x = __shfl_up_sync(0xffffffffu, s, off);
        if (lane >= off) s += x;
    }
    if (lane == 31) wsum[w] = s;
    __syncthreads();
    if (w == 0) {
        int ws = (lane < 16) ? wsum[lane] : 0;
#pragma unroll
        for (int off = 1; off < 16; off <<= 1) {
            int x = __shfl_up_sync(0xffffffffu, ws, off);
            if (lane >= off) ws += x;
        }
        if (lane < 16) wsum[lane] = ws;
    }
    __syncthreads();
    int incl = s + ((w > 0) ? wsum[w - 1] : 0);
    if (i < N_NODES) g_rowptr[i] = incl - v;
    if (t == SCAN_BLK - 1) g_partial[blockIdx.x] = incl;
}

__global__ void scanB_kernel(int nblocks) {
    __shared__ int wsum[8];
    int t = threadIdx.x;
    int lane = t & 31, w = t >> 5;
    int v = (t < nblocks) ? g_partial[t] : 0;
    int s = v;
#pragma unroll
    for (int off = 1; off < 32; off <<= 1) {
        int x = __shfl_up_sync(0xffffffffu, s, off);
        if (lane >= off) s += x;
    }
    if (lane == 31) wsum[w] = s;
    __syncthreads();
    if (w == 0) {
        int ws = (lane < 8) ? wsum[lane] : 0;
#pragma unroll
        for (int off = 1; off < 8; off <<= 1) {
            int x = __shfl_up_sync(0xffffffffu, ws, off);
            if (lane >= off) ws += x;
        }
        if (lane < 8) wsum[lane] = ws;
    }
    __syncthreads();
    int incl = s + ((w > 0) ? wsum[w - 1] : 0);
    if (t < nblocks) g_partial[t] = incl - v;
}

__global__ void scanC_kernel() {
    int i = blockIdx.x * blockDim.x + threadIdx.x;
    if (i < N_NODES) {
        g_rowptr[i] += g_partial[i / SCAN_BLK];
        g_fill[i] = 0;
    }
    if (i == 0) g_rowptr[N_NODES] = N_EDGES;
}

__global__ void csr_fill_kernel(const void* __restrict__ ei) {
    int e = blockIdx.x * blockDim.x + threadIdx.x;
    if (e >= N_EDGES) return;
    int is64 = g_idx64;
    int s = load_idx(ei, e, is64);
    int d = load_idx(ei, (size_t)N_EDGES + e, is64);
    float c = rsqrtf((float)g_deg[s]) * rsqrtf((float)g_deg[d]);
    int pos = g_rowptr[d] + atomicAdd(&g_fill[d], 1);
    g_csr[pos] = make_int2(s, __float_as_int(c));
}

__global__ void init_h0_bias_kernel(const float* __restrict__ b2) {
    int i = blockIdx.x * blockDim.x + threadIdx.x;
    if (i < N_NODES * OUT_CH / 4) {
        const float4* b2v = (const float4*)b2;
        ((float4*)g_h0)[i] = b2v[i & 7];
    }
}

// ---------------- split-precision conversion ----------------
__device__ __forceinline__ void split1(float v, unsigned short& h, unsigned short& l) {
    __nv_bfloat16 hb = __float2bfloat16(v);
    float r = v - __bfloat162float(hb);
    __nv_bfloat16 lb = __float2bfloat16(r);
    h = *(unsigned short*)&hb;
    l = *(unsigned short*)&lb;
}

__global__ void split_w1t_kernel(const float* __restrict__ W1) {
    int i = blockIdx.x * blockDim.x + threadIdx.x;
    if (i >= HID_CH * IN_CH) return;
    int n = i >> 9;
    int k = i & 511;
    unsigned short h, l;
    split1(W1[(size_t)k * HID_CH + n], h, l);
    ((unsigned short*)g_w1t_h)[i] = h;
    ((unsigned short*)g_w1t_l)[i] = l;
}

// ---------------- tensor-core fused MLP (mma.sync, split-bf16) ----------------
#define MMA_BF16(d, a, b0v, b1v)                                             \
    asm volatile(                                                            \
        "mma.sync.aligned.m16n8k16.row.col.f32.bf16.bf16.f32 "               \
        "{%0,%1,%2,%3}, {%4,%5,%6,%7}, {%8,%9}, {%0,%1,%2,%3};"              \
        : "+f"(d[0]), "+f"(d[1]), "+f"(d[2]), "+f"(d[3])                     \
        : "r"(a[0]), "r"(a[1]), "r"(a[2]), "r"(a[3]), "r"(b0v), "r"(b1v))

#define APITCH 40
#define CPITCH 68

__global__ __launch_bounds__(256)
void mlp_mma_kernel(const float* __restrict__ x,
                    const float* __restrict__ b1, const float* __restrict__ W2) {
    __shared__ __align__(16) union {
        struct {
            __nv_bfloat16 Ah[128 * APITCH], Al[128 * APITCH];
            __nv_bfloat16 Bh[128 * APITCH], Bl[128 * APITCH];
        } s1;
        struct { float Cs[128 * CPITCH]; float W2s[64 * 32]; } s2;
    } u;

    const int tid  = threadIdx.x;
    const int warp = tid >> 5;
    const int lane = tid & 31;
    const int wm = warp >> 1;
    const int wn = warp & 1;
    const int g  = lane >> 2;
    const int t  = lane & 3;
    const int brow = blockIdx.x * 128;
    const int bcol = blockIdx.y * 128;

    float acc[2][8][4];
#pragma unroll
    for (int i = 0; i < 2; i++)
#pragma unroll
        for (int j = 0; j < 8; j++)
#pragma unroll
            for (int r = 0; r < 4; r++) acc[i][j][r] = 0.0f;

    float4 pa[4];
    uint4  pbh[2], pbl[2];

    auto load_tile = [&](int k0) {
#pragma unroll
        for (int l = 0; l < 4; l++) {
            int idx = tid + l * 256;
            int row = idx >> 3;
            int seg = idx & 7;
            if (brow + row < N_NODES)
                pa[l] = *(const float4*)&x[(size_t)(brow + row) * IN_CH + k0 + seg * 4];
            else
                pa[l] = make_float4(0.f, 0.f, 0.f, 0.f);
        }
#pragma unroll
        for (int l = 0; l < 2; l++) {
            int idx = tid + l * 256;
            int row = idx >> 2;
            int seg = idx & 3;
            size_t go = (size_t)(bcol + row) * IN_CH + k0 + seg * 8;
            pbh[l] = *(const uint4*)&g_w1t_h[go];
            pbl[l] = *(const uint4*)&g_w1t_l[go];
        }
    };

    auto store_tile = [&]() {
#pragma unroll
        for (int l = 0; l < 4; l++) {
            int idx = tid + l * 256;
            int row = idx >> 3;
            int seg = idx & 7;
            ushort4 hh, ll;
            split1(pa[l].x, hh.x, ll.x);
            split1(pa[l].y, hh.y, ll.y);
            split1(pa[l].z, hh.z, ll.z);
            split1(pa[l].w, hh.w, ll.w);
            *(ushort4*)&u.s1.Ah[row * APITCH + seg * 4] = hh;
            *(ushort4*)&u.s1.Al[row * APITCH + seg * 4] = ll;
        }
#pragma unroll
        for (int l = 0; l < 2; l++) {
            int idx = tid + l * 256;
            int row = idx >> 2;
            int seg = idx & 3;
            *(uint4*)&u.s1.Bh[row * APITCH + seg * 8] = pbh[l];
            *(uint4*)&u.s1.Bl[row * APITCH + seg * 8] = pbl[l];
        }
    };

    load_tile(0);
    store_tile();
    __syncthreads();

    for (int k0 = 0; k0 < IN_CH; k0 += 32) {
        const bool more = (k0 + 32) < IN_CH;
        if (more) load_tile(k0 + 32);

#pragma unroll
        for (int kk = 0; kk < 32; kk += 16) {
            uint32_t ah[2][4], al[2][4];
#pragma unroll
            for (int i = 0; i < 2; i++) {
                int r = wm * 32 + i * 16 + g;
                int base = r * APITCH + kk + t * 2;
                ah[i][0] = *(const uint32_t*)&u.s1.Ah[base];
                ah[i][1] = *(const uint32_t*)&u.s1.Ah[base + 8 * APITCH];
                ah[i][2] = *(const uint32_t*)&u.s1.Ah[base + 8];
                ah[i][3] = *(const uint32_t*)&u.s1.Ah[base + 8 * APITCH + 8];
                al[i][0] = *(const uint32_t*)&u.s1.Al[base];
                al[i][1] = *(const uint32_t*)&u.s1.Al[base + 8 * APITCH];
                al[i][2] = *(const uint32_t*)&u.s1.Al[base + 8];
                al[i][3] = *(const uint32_t*)&u.s1.Al[base + 8 * APITCH + 8];
            }
#pragma unroll
            for (int j = 0; j < 8; j++) {
                int n = wn * 64 + j * 8 + g;
                int bb = n * APITCH + kk + t * 2;
                uint32_t bh0 = *(const uint32_t*)&u.s1.Bh[bb];
                uint32_t bh1 = *(const uint32_t*)&u.s1.Bh[bb + 8];
                uint32_t bl0 = *(const uint32_t*)&u.s1.Bl[bb];
                uint32_t bl1 = *(const uint32_t*)&u.s1.Bl[bb + 8];
#pragma unroll
                for (int i = 0; i < 2; i++) {
                    MMA_BF16(acc[i][j], ah[i], bh0, bh1);
                    MMA_BF16(acc[i][j], ah[i], bl0, bl1);
                    MMA_BF16(acc[i][j], al[i], bh0, bh1);
                }
            }
        }
        __syncthreads();
        if (more) {
            store_tile();
            __syncthreads();
        }
    }

    // ---- stage 2: relu(acc + b1) @ W2-slice, two 64-col halves ----
    const int c    = tid & 31;
    const int rgrp = tid >> 5;
    float sum[16];
#pragma unroll
    for (int rr = 0; rr < 16; rr++) sum[rr] = 0.0f;

#pragma unroll
    for (int h = 0; h < 2; h++) {
        __syncthreads();
        if (wn == h) {
#pragma unroll
            for (int i = 0; i < 2; i++)
#pragma unroll
                for (int j = 0; j < 8; j++) {
                    int row = wm * 32 + i * 16 + g;
                    int col = j * 8 + t * 2;
                    float bias0 = b1[bcol + h * 64 + col];
                    float bias1 = b1[bcol + h * 64 + col + 1];
                    float2 v0, v1;
                    v0.x = fmaxf(acc[i][j][0] + bias0, 0.0f);
                    v0.y = fmaxf(acc[i][j][1] + bias1, 0.0f);
                    v1.x = fmaxf(acc[i][j][2] + bias0, 0.0f);
                    v1.y = fmaxf(acc[i][j][3] + bias1, 0.0f);
                    *(float2*)&u.s2.Cs[row * CPITCH + col]       = v0;
                    *(float2*)&u.s2.Cs[(row + 8) * CPITCH + col] = v1;
                }
        }
#pragma unroll
        for (int l = 0; l < 8; l++) {
            int q = tid + l * 256;
            u.s2.W2s[q] = W2[(size_t)(bcol + h * 64 + (q >> 5)) * OUT_CH + (q & 31)];
        }
        __syncthreads();

#pragma unroll
        for (int k4 = 0; k4 < 16; k4++) {
            float w0 = u.s2.W2s[(k4 * 4 + 0) * 32 + c];
            float w1 = u.s2.W2s[(k4 * 4 + 1) * 32 + c];
            float w2 = u.s2.W2s[(k4 * 4 + 2) * 32 + c];
            float w3 = u.s2.W2s[(k4 * 4 + 3) * 32 + c];
#pragma unroll
            for (int rr = 0; rr < 16; rr++) {
                float4 cv = *(const float4*)&u.s2.Cs[(rgrp * 16 + rr) * CPITCH + k4 * 4];
                sum[rr] += cv.x * w0 + cv.y * w1 + cv.z * w2 + cv.w * w3;
            }
        }
    }

#pragma unroll
    for (int rr = 0; rr < 16; rr++) {
        int grow = brow + rgrp * 16 + rr;
        if (grow < N_NODES)
            atomicAdd(&g_h0[(size_t)grow * OUT_CH + c], sum[rr]);
    }
}

// ---------------- APPNP propagation: fused pull + combine ----------------
// Intermediate h buffers stored in fp16 (accumulation stays fp32; h0 fp32).
// CUR: 0 = g_h0 (fp32), 1 = g_ha16, 2 = g_hb16.  NXT: 1/2 = fp16 buf, 3 = out.
template <int CUR, int NXT>
__global__ void pull_kernel(float* __restrict__ out) {
    const __half* __restrict__ h16 = (CUR == 1) ? g_ha16 : g_hb16;

    int t = blockIdx.x * blockDim.x + threadIdx.x;
    int node = t >> 3;
    int q = t & 7;
    if (node >= N_NODES) return;

    int beg = g_rowptr[node];
    int end = g_rowptr[node + 1];

    float4 acc = make_float4(0.f, 0.f, 0.f, 0.f);
    if (CUR == 0) {
#pragma unroll 4
        for (int i = beg; i < end; i++) {
            int2 ed = __ldg(&g_csr[i]);
            float cf = __int_as_float(ed.y);
            float4 hv = *(const float4*)&g_h0[(size_t)ed.x * OUT_CH + q * 4];
            acc.x += cf * hv.x;
            acc.y += cf * hv.y;
            acc.z += cf * hv.z;
            acc.w += cf * hv.w;
        }
    } else {
#pragma unroll 4
        for (int i = beg; i < end; i++) {
            int2 ed = __ldg(&g_csr[i]);
            float cf = __int_as_float(ed.y);
            uint2 raw = __ldg((const uint2*)&h16[(size_t)ed.x * OUT_CH + q * 4]);
            float2 f0 = __half22float2(*(__half2*)&raw.x);
            float2 f1 = __half22float2(*(__half2*)&raw.y);
            acc.x += cf * f0.x;
            acc.y += cf * f0.y;
            acc.z += cf * f1.x;
            acc.w += cf * f1.y;
        }
    }

    size_t i4 = (size_t)node * 8 + q;
    float sc = g_selfc[node];
    float4 h0v = ((const float4*)g_h0)[i4];
    float4 hc;
    if (CUR == 0) {
        hc = h0v;   // step 0: h_cur == h0
    } else {
        uint2 raw = *(const uint2*)&h16[(size_t)node * OUT_CH + q * 4];
        float2 f0 = __half22float2(*(__half2*)&raw.x);
        float2 f1 = __half22float2(*(__half2*)&raw.y);
        hc = make_float4(f0.x, f0.y, f1.x, f1.y);
    }

    float4 r;
    r.x = ALPHA * h0v.x + (1.0f - ALPHA) * (acc.x + sc * hc.x);
    r.y = ALPHA * h0v.y + (1.0f - ALPHA) * (acc.y + sc * hc.y);
    r.z = ALPHA * h0v.z + (1.0f - ALPHA) * (acc.z + sc * hc.z);
    r.w = ALPHA * h0v.w + (1.0f - ALPHA) * (acc.w + sc * hc.w);

    if (NXT == 3) {
        ((float4*)out)[i4] = r;
    } else {
        __half* __restrict__ hn = (NXT == 1) ? g_ha16 : g_hb16;
        __half2 lo = __floats2half2_rn(r.x, r.y);
        __half2 hi = __floats2half2_rn(r.z, r.w);
        uint2 st;
        st.x = *(unsigned*)&lo;
        st.y = *(unsigned*)&hi;
        *(uint2*)&hn[(size_t)node * OUT_CH + q * 4] = st;
    }
}

// ---------------- host launch ----------------
extern "C" void kernel_launch(void* const* d_in, const int* in_sizes, int n_in,
                              void* d_out, int out_size) {
    const float* x = nullptr;  const void* ei = nullptr;
    const float* W1 = nullptr; const float* b1 = nullptr;
    const float* W2 = nullptr; const float* b2 = nullptr;
    for (int i = 0; i < n_in; i++) {
        switch (in_sizes[i]) {
            case N_NODES * IN_CH:   x  = (const float*)d_in[i]; break;
            case 2 * N_EDGES:       ei = d_in[i]; break;
            case IN_CH * HID_CH:    W1 = (const float*)d_in[i]; break;
            case HID_CH:            b1 = (const float*)d_in[i]; break;
            case HID_CH * OUT_CH:   W2 = (const float*)d_in[i]; break;
            case OUT_CH:            b2 = (const float*)d_in[i]; break;
            default: break;
        }
    }
    float* out = (float*)d_out;

    const int NC4 = N_NODES * OUT_CH / 4;
    const int SCAN_NB = (N_NODES + SCAN_BLK - 1) / SCAN_BLK;  // 196

    static cudaStream_t s2 = [] {
        cudaStream_t s;
        cudaStreamCreateWithFlags(&s, cudaStreamNonBlocking);
        return s;
    }();
    static cudaEvent_t evF = [] {
        cudaEvent_t e;
        cudaEventCreateWithFlags(&e, cudaEventDisableTiming);
        return e;
    }();
    static cudaEvent_t evJ = [] {
        cudaEvent_t e;
        cudaEventCreateWithFlags(&e, cudaEventDisableTiming);
        return e;
    }();

    // ---- fork: branch B (MLP chain) on s2, branch A (CSR chain) on default ----
    cudaEventRecord(evF, 0);
    cudaStreamWaitEvent(s2, evF, 0);

    split_w1t_kernel<<<(HID_CH * IN_CH + 255) / 256, 256, 0, s2>>>(W1);
    init_h0_bias_kernel<<<(NC4 + 255) / 256, 256, 0, s2>>>(b2);
    {
        dim3 grid((N_NODES + 127) / 128, HID_CH / 128);
        mlp_mma_kernel<<<grid, 256, 0, s2>>>(x, b1, W2);
    }
    cudaEventRecord(evJ, s2);

    detect_dtype_kernel<<<1, 32>>>((const int*)ei);
    init_deg_kernel<<<(N_NODES + 255) / 256, 256>>>();
    deg_edges_kernel<<<(N_EDGES + 255) / 256, 256>>>(ei);
    scanA_kernel<<<SCAN_NB, SCAN_BLK>>>();
    scanB_kernel<<<1, 256>>>(SCAN_NB);
    scanC_kernel<<<(N_NODES + 255) / 256, 256>>>();
    csr_fill_kernel<<<(N_EDGES + 255) / 256, 256>>>(ei);

    // ---- join ----
    cudaStreamWaitEvent(0, evJ, 0);

    // propagation: 10 fused pull+combine steps (fp16 intermediate buffers)
    const int PB = (int)(((size_t)N_NODES * 8 + 255) / 256);  // 3125

    pull_kernel<0, 1><<<PB, 256>>>(out); // k=0  (fp32 h0 -> fp16 ha)
    pull_kernel<1, 2><<<PB, 256>>>(out); // k=1
    pull_kernel<2, 1><<<PB, 256>>>(out); // k=2
    pull_kernel<1, 2><<<PB, 256>>>(out); // k=3
    pull_kernel<2, 1><<<PB, 256>>>(out); // k=4
    pull_kernel<1, 2><<<PB, 256>>>(out); // k=5
    pull_kernel<2, 1><<<PB, 256>>>(out); // k=6
    pull_kernel<1, 2><<<PB, 256>>>(out); // k=7
    pull_kernel<2, 1><<<PB, 256>>>(out); // k=8
    pull_kernel<1, 3><<<PB, 256>>>(out); // k=9 -> out (fp32)
}

// round 14
// speedup vs baseline: 1.2099x; 1.0882x over previous
#include <cuda_runtime.h>
#include <cuda_bf16.h>
#include <cuda_fp16.h>
#include <cstdint>

// ---------------- problem constants ----------------
#define N_NODES 100000
#define IN_CH   512
#define HID_CH  256
#define OUT_CH  32
#define N_EDGES 1600000
#define K_STEPS 10
#define ALPHA   0.1f

// ---------------- device scratch (no allocations allowed) ----------------
__device__ float g_h0[(size_t)N_NODES * OUT_CH];
__device__ __align__(16) __half g_ha16[(size_t)N_NODES * OUT_CH];  // ping (fp16)
__device__ __align__(16) __half g_hb16[(size_t)N_NODES * OUT_CH];  // pong (fp16)
__device__ int   g_deg[N_NODES];
__device__ float g_selfc[N_NODES];
__device__ int   g_idx64;

// CSR (dst-sorted) for pull aggregation
__device__ int   g_rowptr[N_NODES + 1];
__device__ int   g_fill[N_NODES];
__device__ int   g_partial[256];
__device__ int2  g_csr[N_EDGES];       // {src, coef_bits}

// split-bf16 W1^T for the tensor-core GEMM ([n][k])
__device__ __align__(16) __nv_bfloat16 g_w1t_h[(size_t)HID_CH * IN_CH];
__device__ __align__(16) __nv_bfloat16 g_w1t_l[(size_t)HID_CH * IN_CH];

// ---------------- dtype detection ----------------
__global__ void detect_dtype_kernel(const int* __restrict__ ei32) {
    int t = threadIdx.x;
    int any = 0;
    for (int i = t; i < 1024; i += 32) any |= ei32[2 * i + 1];
#pragma unroll
    for (int o = 16; o; o >>= 1) any |= __shfl_xor_sync(0xffffffffu, any, o);
    if (t == 0) g_idx64 = (any == 0) ? 1 : 0;
}

__device__ __forceinline__ int load_idx(const void* ei, size_t pos, int is64) {
    long long v = is64 ? ((const long long*)ei)[pos] : (long long)((const int*)ei)[pos];
    if (v < 0) v = 0;
    if (v >= N_NODES) v = N_NODES - 1;
    return (int)v;
}

// ---------------- degree ----------------
__global__ void init_deg_kernel() {
    int i = blockIdx.x * blockDim.x + threadIdx.x;
    if (i < N_NODES) g_deg[i] = 1;  // self-loop
}

__global__ void deg_edges_kernel(const void* __restrict__ ei) {
    int e = blockIdx.x * blockDim.x + threadIdx.x;
    if (e >= N_EDGES) return;
    int is64 = g_idx64;
    atomicAdd(&g_deg[load_idx(ei, (size_t)N_EDGES + e, is64)], 1);
}

// ---------------- CSR build: warp-shuffle scans + fused fill ----------------
#define SCAN_BLK 512
__global__ void scanA_kernel() {   // exclusive scan of (deg-1) + selfc
    __shared__ int wsum[16];
    int t = threadIdx.x;
    int i = blockIdx.x * SCAN_BLK + t;
    int v = (i < N_NODES) ? (g_deg[i] - 1) : 0;
    if (i < N_NODES) g_selfc[i] = 1.0f / (float)(v + 1);
    int lane = t & 31, w = t >> 5;
    int s = v;
#pragma unroll
    for (int off = 1; off < 32; off <<= 1) {
        int x = __shfl_up_sync(0xffffffffu, s, off);
        if (lane >= off) s += x;
    }
    if (lane == 31) wsum[w] = s;
    __syncthreads();
    if (w == 0) {
        int ws = (lane < 16) ? wsum[lane] : 0;
#pragma unroll
        for (int off = 1; off < 16; off <<= 1) {
            int x = __shfl_up_sync(0xffffffffu, ws, off);
            if (lane >= off) ws += x;
        }
        if (lane < 16) wsum[lane] = ws;
    }
    __syncthreads();
    int incl = s + ((w > 0) ? wsum[w - 1] : 0);
    if (i < N_NODES) g_rowptr[i] = incl - v;
    if (t == SCAN_BLK - 1) g_partial[blockIdx.x] = incl;
}

__global__ void scanB_kernel(int nblocks) {
    __shared__ int wsum[8];
    int t = threadIdx.x;
    int lane = t & 31, w = t >> 5;
    int v = (t < nblocks) ? g_partial[t] : 0;
    int s = v;
#pragma unroll
    for (int off = 1; off < 32; off <<= 1) {
        int x = __shfl_up_sync(0xffffffffu, s, off);
        if (lane >= off) s += x;
    }
    if (lane == 31) wsum[w] = s;
    __syncthreads();
    if (w == 0) {
        int ws = (lane < 8) ? wsum[lane] : 0;
#pragma unroll
        for (int off = 1; off < 8; off <<= 1) {
            int x = __shfl_up_sync(0xffffffffu, ws, off);
            if (lane >= off) ws += x;
        }
        if (lane < 8) wsum[lane] = ws;
    }
    __syncthreads();
    int incl = s + ((w > 0) ? wsum[w - 1] : 0);
    if (t < nblocks) g_partial[t] = incl - v;
}

__global__ void scanC_kernel() {
    int i = blockIdx.x * blockDim.x + threadIdx.x;
    if (i < N_NODES) {
        g_rowptr[i] += g_partial[i / SCAN_BLK];
        g_fill[i] = 0;
    }
    if (i == 0) g_rowptr[N_NODES] = N_EDGES;
}

__global__ void csr_fill_kernel(const void* __restrict__ ei) {
    int e = blockIdx.x * blockDim.x + threadIdx.x;
    if (e >= N_EDGES) return;
    int is64 = g_idx64;
    int s = load_idx(ei, e, is64);
    int d = load_idx(ei, (size_t)N_EDGES + e, is64);
    float c = rsqrtf((float)g_deg[s]) * rsqrtf((float)g_deg[d]);
    int pos = g_rowptr[d] + atomicAdd(&g_fill[d], 1);
    g_csr[pos] = make_int2(s, __float_as_int(c));
}

// ---------------- split-precision conversion ----------------
__device__ __forceinline__ void split1(float v, unsigned short& h, unsigned short& l) {
    __nv_bfloat16 hb = __float2bfloat16(v);
    float r = v - __bfloat162float(hb);
    __nv_bfloat16 lb = __float2bfloat16(r);
    h = *(unsigned short*)&hb;
    l = *(unsigned short*)&lb;
}

__global__ void split_w1t_kernel(const float* __restrict__ W1) {
    int i = blockIdx.x * blockDim.x + threadIdx.x;
    if (i >= HID_CH * IN_CH) return;
    int n = i >> 9;
    int k = i & 511;
    unsigned short h, l;
    split1(W1[(size_t)k * HID_CH + n], h, l);
    ((unsigned short*)g_w1t_h)[i] = h;
    ((unsigned short*)g_w1t_l)[i] = l;
}

// ---------------- tensor-core fused MLP (mma.sync, split-bf16) ----------------
// One block: 128 rows x FULL 256 hidden (x read once), 512 threads / 16 warps.
// Stage 2: 4 sequential 64-col rounds, full dot product in regs, direct store
// of h0 = relu(xW1+b1)@W2 + b2 (no atomics, no h0 pre-init).
#define MMA_BF16(d, a, b0v, b1v)                                             \
    asm volatile(                                                            \
        "mma.sync.aligned.m16n8k16.row.col.f32.bf16.bf16.f32 "               \
        "{%0,%1,%2,%3}, {%4,%5,%6,%7}, {%8,%9}, {%0,%1,%2,%3};"              \
        : "+f"(d[0]), "+f"(d[1]), "+f"(d[2]), "+f"(d[3])                     \
        : "r"(a[0]), "r"(a[1]), "r"(a[2]), "r"(a[3]), "r"(b0v), "r"(b1v))

#define APITCH 40
#define CPITCH 68
// dynamic smem layout (bytes):
//   stage1: Ah @0 (10240), Al @10240, Bh @20480 (20480), Bl @40960  -> 61440
//   stage2: Cs @0 (128*68*4=34816), W2s @34816 (8192)               -> 43008
#define OFF_AL 10240
#define OFF_BH 20480
#define OFF_BL 40960
#define OFF_W2 34816
#define MLP_SMEM 61440

__global__ __launch_bounds__(512, 1)
void mlp_mma_kernel(const float* __restrict__ x, const float* __restrict__ b1,
                    const float* __restrict__ W2, const float* __restrict__ b2) {
    extern __shared__ __align__(16) char sm[];
    __nv_bfloat16* Ah = (__nv_bfloat16*)sm;
    __nv_bfloat16* Al = (__nv_bfloat16*)(sm + OFF_AL);
    __nv_bfloat16* Bh = (__nv_bfloat16*)(sm + OFF_BH);
    __nv_bfloat16* Bl = (__nv_bfloat16*)(sm + OFF_BL);
    float* Cs  = (float*)sm;
    float* W2s = (float*)(sm + OFF_W2);

    const int tid  = threadIdx.x;
    const int warp = tid >> 5;
    const int lane = tid & 31;
    const int wm = warp >> 2;          // 0..3: 32-row slab
    const int wn = warp & 3;           // 0..3: 64-col slab
    const int g  = lane >> 2;
    const int t  = lane & 3;
    const int brow = blockIdx.x * 128;

    float acc[2][8][4];
#pragma unroll
    for (int i = 0; i < 2; i++)
#pragma unroll
        for (int j = 0; j < 8; j++)
#pragma unroll
            for (int r = 0; r < 4; r++) acc[i][j][r] = 0.0f;

    float4 pa[2];
    uint4  pbh[2], pbl[2];

    auto load_tile = [&](int k0) {
#pragma unroll
        for (int l = 0; l < 2; l++) {           // A: 128 rows x 32k fp32 = 1024 f4
            int idx = tid + l * 512;
            int row = idx >> 3;
            int seg = idx & 7;
            if (brow + row < N_NODES)
                pa[l] = *(const float4*)&x[(size_t)(brow + row) * IN_CH + k0 + seg * 4];
            else
                pa[l] = make_float4(0.f, 0.f, 0.f, 0.f);
        }
#pragma unroll
        for (int l = 0; l < 2; l++) {           // B: 256 rows x 32k bf16 = 1024 u4
            int idx = tid + l * 512;
            int row = idx >> 2;
            int seg = idx & 3;
            size_t go = (size_t)row * IN_CH + k0 + seg * 8;
            pbh[l] = *(const uint4*)&g_w1t_h[go];
            pbl[l] = *(const uint4*)&g_w1t_l[go];
        }
    };

    auto store_tile = [&]() {
#pragma unroll
        for (int l = 0; l < 2; l++) {
            int idx = tid + l * 512;
            int row = idx >> 3;
            int seg = idx & 7;
            ushort4 hh, ll;
            split1(pa[l].x, hh.x, ll.x);
            split1(pa[l].y, hh.y, ll.y);
            split1(pa[l].z, hh.z, ll.z);
            split1(pa[l].w, hh.w, ll.w);
            *(ushort4*)&Ah[row * APITCH + seg * 4] = hh;
            *(ushort4*)&Al[row * APITCH + seg * 4] = ll;
        }
#pragma unroll
        for (int l = 0; l < 2; l++) {
            int idx = tid + l * 512;
            int row = idx >> 2;
            int seg = idx & 3;
            *(uint4*)&Bh[row * APITCH + seg * 8] = pbh[l];
            *(uint4*)&Bl[row * APITCH + seg * 8] = pbl[l];
        }
    };

    load_tile(0);
    store_tile();
    __syncthreads();

    for (int k0 = 0; k0 < IN_CH; k0 += 32) {
        const bool more = (k0 + 32) < IN_CH;
        if (more) load_tile(k0 + 32);

#pragma unroll
        for (int kk = 0; kk < 32; kk += 16) {
            uint32_t ah[2][4], al[2][4];
#pragma unroll
            for (int i = 0; i < 2; i++) {
                int r = wm * 32 + i * 16 + g;
                int base = r * APITCH + kk + t * 2;
                ah[i][0] = *(const uint32_t*)&Ah[base];
                ah[i][1] = *(const uint32_t*)&Ah[base + 8 * APITCH];
                ah[i][2] = *(const uint32_t*)&Ah[base + 8];
                ah[i][3] = *(const uint32_t*)&Ah[base + 8 * APITCH + 8];
                al[i][0] = *(const uint32_t*)&Al[base];
                al[i][1] = *(const uint32_t*)&Al[base + 8 * APITCH];
                al[i][2] = *(const uint32_t*)&Al[base + 8];
                al[i][3] = *(const uint32_t*)&Al[base + 8 * APITCH + 8];
            }
#pragma unroll
            for (int j = 0; j < 8; j++) {
                int n = wn * 64 + j * 8 + g;
                int bb = n * APITCH + kk + t * 2;
                uint32_t bh0 = *(const uint32_t*)&Bh[bb];
                uint32_t bh1 = *(const uint32_t*)&Bh[bb + 8];
                uint32_t bl0 = *(const uint32_t*)&Bl[bb];
                uint32_t bl1 = *(const uint32_t*)&Bl[bb + 8];
#pragma unroll
                for (int i = 0; i < 2; i++) {
                    MMA_BF16(acc[i][j], ah[i], bh0, bh1);
                    MMA_BF16(acc[i][j], ah[i], bl0, bl1);
                    MMA_BF16(acc[i][j], al[i], bh0, bh1);
                }
            }
        }
        __syncthreads();
        if (more) {
            store_tile();
            __syncthreads();
        }
    }

    // ---- stage 2: relu(acc + b1) @ W2, four 64-col rounds, direct h0 store ----
    const int c    = tid & 31;
    const int rgrp = tid >> 5;      // 0..15, 8 rows each
    float sum[8];
#pragma unroll
    for (int rr = 0; rr < 8; rr++) sum[rr] = 0.0f;

#pragma unroll
    for (int h = 0; h < 4; h++) {
        __syncthreads();            // previous round consumed / stage-1 smem dead
        if (wn == h) {
#pragma unroll
            for (int i = 0; i < 2; i++)
#pragma unroll
                for (int j = 0; j < 8; j++) {
                    int row = wm * 32 + i * 16 + g;
                    int col = j * 8 + t * 2;
                    float bias0 = b1[h * 64 + col];
                    float bias1 = b1[h * 64 + col + 1];
                    float2 v0, v1;
                    v0.x = fmaxf(acc[i][j][0] + bias0, 0.0f);
                    v0.y = fmaxf(acc[i][j][1] + bias1, 0.0f);
                    v1.x = fmaxf(acc[i][j][2] + bias0, 0.0f);
                    v1.y = fmaxf(acc[i][j][3] + bias1, 0.0f);
                    *(float2*)&Cs[row * CPITCH + col]       = v0;
                    *(float2*)&Cs[(row + 8) * CPITCH + col] = v1;
                }
        }
#pragma unroll
        for (int l = 0; l < 4; l++) {   // W2 slice [64,32]
            int q2 = tid + l * 512;
            W2s[q2] = W2[(size_t)(h * 64 + (q2 >> 5)) * OUT_CH + (q2 & 31)];
        }
        __syncthreads();

#pragma unroll
        for (int k4 = 0; k4 < 16; k4++) {
            float w0 = W2s[(k4 * 4 + 0) * 32 + c];
            float w1 = W2s[(k4 * 4 + 1) * 32 + c];
            float w2 = W2s[(k4 * 4 + 2) * 32 + c];
            float w3 = W2s[(k4 * 4 + 3) * 32 + c];
#pragma unroll
            for (int rr = 0; rr < 8; rr++) {
                float4 cv = *(const float4*)&Cs[(rgrp * 8 + rr) * CPITCH + k4 * 4];
                sum[rr] += cv.x * w0 + cv.y * w1 + cv.z * w2 + cv.w * w3;
            }
        }
    }

    float bias2 = b2[c];
#pragma unroll
    for (int rr = 0; rr < 8; rr++) {
        int grow = brow + rgrp * 8 + rr;
        if (grow < N_NODES)
            g_h0[(size_t)grow * OUT_CH + c] = sum[rr] + bias2;
    }
}

// ---------------- APPNP propagation: fused pull + combine ----------------
// fp16 intermediates; state loads hoisted; batch-4 csr prefetch pipeline.
// CUR: 0 = g_h0 (fp32), 1 = g_ha16, 2 = g_hb16.  NXT: 1/2 = fp16 buf, 3 = out.
template <int CUR, int NXT>
__global__ void pull_kernel(float* __restrict__ out) {
    const __half* __restrict__ h16 = (CUR == 1) ? g_ha16 : g_hb16;

    int t = blockIdx.x * blockDim.x + threadIdx.x;
    int node = t >> 3;
    int q = t & 7;
    if (node >= N_NODES) return;

    int beg = g_rowptr[node];
    int end = g_rowptr[node + 1];

    // hoisted per-node state (overlaps with the gather loop)
    size_t i4 = (size_t)node * 8 + q;
    float sc = g_selfc[node];
    float4 h0v = ((const float4*)g_h0)[i4];
    float4 hc;
    if (CUR == 0) {
        hc = h0v;
    } else {
        uint2 raw = *(const uint2*)&h16[(size_t)node * OUT_CH + q * 4];
        float2 f0 = __half22float2(*(__half2*)&raw.x);
        float2 f1 = __half22float2(*(__half2*)&raw.y);
        hc = make_float4(f0.x, f0.y, f1.x, f1.y);
    }

    float4 acc = make_float4(0.f, 0.f, 0.f, 0.f);
    int2 eb[4];
    int i = beg;
    int nb = end - i; if (nb > 4) nb = 4;
#pragma unroll
    for (int k = 0; k < 4; k++)
        if (k < nb) eb[k] = __ldg(&g_csr[i + k]);

    while (nb > 0) {
        int inext = i + nb;
        int nnext = end - inext; if (nnext > 4) nnext = 4;
        int2 en[4];
#pragma unroll
        for (int k = 0; k < 4; k++)
            if (k < nnext) en[k] = __ldg(&g_csr[inext + k]);   // prefetch next batch

#pragma unroll
        for (int k = 0; k < 4; k++) {
            if (k < nb) {
                float cf = __int_as_float(eb[k].y);
                if (CUR == 0) {
                    float4 hv = __ldg((const float4*)&g_h0[(size_t)eb[k].x * OUT_CH + q * 4]);
                    acc.x += cf * hv.x;
                    acc.y += cf * hv.y;
                    acc.z += cf * hv.z;
                    acc.w += cf * hv.w;
                } else {
                    uint2 raw = __ldg((const uint2*)&h16[(size_t)eb[k].x * OUT_CH + q * 4]);
                    float2 f0 = __half22float2(*(__half2*)&raw.x);
                    float2 f1 = __half22float2(*(__half2*)&raw.y);
                    acc.x += cf * f0.x;
                    acc.y += cf * f0.y;
                    acc.z += cf * f1.x;
                    acc.w += cf * f1.y;
                }
            }
        }
#pragma unroll
        for (int k = 0; k < 4; k++) eb[k] = en[k];
        i = inext;
        nb = nnext;
    }

    float4 r;
    r.x = ALPHA * h0v.x + (1.0f - ALPHA) * (acc.x + sc * hc.x);
    r.y = ALPHA * h0v.y + (1.0f - ALPHA) * (acc.y + sc * hc.y);
    r.z = ALPHA * h0v.z + (1.0f - ALPHA) * (acc.z + sc * hc.z);
    r.w = ALPHA * h0v.w + (1.0f - ALPHA) * (acc.w + sc * hc.w);

    if (NXT == 3) {
        ((float4*)out)[i4] = r;
    } else {
        __half* __restrict__ hn = (NXT == 1) ? g_ha16 : g_hb16;
        __half2 lo = __floats2half2_rn(r.x, r.y);
        __half2 hi = __floats2half2_rn(r.z, r.w);
        uint2 st;
        st.x = *(unsigned*)&lo;
        st.y = *(unsigned*)&hi;
        *(uint2*)&hn[(size_t)node * OUT_CH + q * 4] = st;
    }
}

// ---------------- host launch ----------------
extern "C" void kernel_launch(void* const* d_in, const int* in_sizes, int n_in,
                              void* d_out, int out_size) {
    const float* x = nullptr;  const void* ei = nullptr;
    const float* W1 = nullptr; const float* b1 = nullptr;
    const float* W2 = nullptr; const float* b2 = nullptr;
    for (int i = 0; i < n_in; i++) {
        switch (in_sizes[i]) {
            case N_NODES * IN_CH:   x  = (const float*)d_in[i]; break;
            case 2 * N_EDGES:       ei = d_in[i]; break;
            case IN_CH * HID_CH:    W1 = (const float*)d_in[i]; break;
            case HID_CH:            b1 = (const float*)d_in[i]; break;
            case HID_CH * OUT_CH:   W2 = (const float*)d_in[i]; break;
            case OUT_CH:            b2 = (const float*)d_in[i]; break;
            default: break;
        }
    }
    float* out = (float*)d_out;

    const int SCAN_NB = (N_NODES + SCAN_BLK - 1) / SCAN_BLK;  // 196

    static cudaStream_t s2 = [] {
        cudaStream_t s;
        cudaStreamCreateWithFlags(&s, cudaStreamNonBlocking);
        return s;
    }();
    static cudaEvent_t evF = [] {
        cudaEvent_t e;
        cudaEventCreateWithFlags(&e, cudaEventDisableTiming);
        return e;
    }();
    static cudaEvent_t evJ = [] {
        cudaEvent_t e;
        cudaEventCreateWithFlags(&e, cudaEventDisableTiming);
        return e;
    }();

    cudaFuncSetAttribute(mlp_mma_kernel,
                         cudaFuncAttributeMaxDynamicSharedMemorySize, MLP_SMEM);

    // ---- fork: branch B (MLP chain) on s2, branch A (CSR chain) on default ----
    cudaEventRecord(evF, 0);
    cudaStreamWaitEvent(s2, evF, 0);

    split_w1t_kernel<<<(HID_CH * IN_CH + 255) / 256, 256, 0, s2>>>(W1);
    mlp_mma_kernel<<<(N_NODES + 127) / 128, 512, MLP_SMEM, s2>>>(x, b1, W2, b2);
    cudaEventRecord(evJ, s2);

    detect_dtype_kernel<<<1, 32>>>((const int*)ei);
    init_deg_kernel<<<(N_NODES + 255) / 256, 256>>>();
    deg_edges_kernel<<<(N_EDGES + 255) / 256, 256>>>(ei);
    scanA_kernel<<<SCAN_NB, SCAN_BLK>>>();
    scanB_kernel<<<1, 256>>>(SCAN_NB);
    scanC_kernel<<<(N_NODES + 255) / 256, 256>>>();
    csr_fill_kernel<<<(N_EDGES + 255) / 256, 256>>>(ei);

    // ---- join ----
    cudaStreamWaitEvent(0, evJ, 0);

    // propagation: 10 fused pull+combine steps (fp16 intermediate buffers)
    const int PB = (int)(((size_t)N_NODES * 8 + 255) / 256);  // 3125

    pull_kernel<0, 1><<<PB, 256>>>(out); // k=0  (fp32 h0 -> fp16 ha)
    pull_kernel<1, 2><<<PB, 256>>>(out); // k=1
    pull_kernel<2, 1><<<PB, 256>>>(out); // k=2
    pull_kernel<1, 2><<<PB, 256>>>(out); // k=3
    pull_kernel<2, 1><<<PB, 256>>>(out); // k=4
    pull_kernel<1, 2><<<PB, 256>>>(out); // k=5
    pull_kernel<2, 1><<<PB, 256>>>(out); // k=6
    pull_kernel<1, 2><<<PB, 256>>>(out); // k=7
    pull_kernel<2, 1><<<PB, 256>>>(out); // k=8
    pull_kernel<1, 3><<<PB, 256>>>(out); // k=9 -> out (fp32)
}